// round 6
// baseline (speedup 1.0000x reference)
#include <cuda_runtime.h>
#include <cuda_bf16.h>
#include <cstdint>
#include <math.h>

#define S_LEN 4096
#define DIM   128
#define BQ    64
#define BK    64
#define NT    256
#define NT64  (S_LEN / 64)
#define TILEB 16384

// K/V pre-converted scratch: [B][tile][Kh,Kl,Vh,Vl][16KB] = 16MB
__device__ __align__(16) char g_kv[4 * NT64 * 4 * TILEB];

// per-CTA smem byte offsets
#define OQH 0
#define OQL 16384
#define OKH 32768            // Kh(16K) + Kl(16K), cp.async image
#define OVH 65536            // Vh(16K) + Vl(16K)
#define OVL 81920
#define OPH 98304
#define OPL 106496
#define SMEM_BYTES 114688
#define ORS OKH
#define OSTG (OKH + 1024)

__device__ __forceinline__ uint32_t s2u(const void* p) {
    uint32_t a;
    asm("{ .reg .u64 t; cvta.to.shared.u64 t, %1; cvt.u32.u64 %0, t; }" : "=r"(a) : "l"(p));
    return a;
}
__device__ __forceinline__ void ldm4(uint32_t a, uint32_t& r0, uint32_t& r1, uint32_t& r2, uint32_t& r3) {
    asm volatile("ldmatrix.sync.aligned.m8n8.x4.shared.b16 {%0,%1,%2,%3}, [%4];"
                 : "=r"(r0), "=r"(r1), "=r"(r2), "=r"(r3) : "r"(a));
}
__device__ __forceinline__ void ldm4t(uint32_t a, uint32_t& r0, uint32_t& r1, uint32_t& r2, uint32_t& r3) {
    asm volatile("ldmatrix.sync.aligned.m8n8.x4.trans.shared.b16 {%0,%1,%2,%3}, [%4];"
                 : "=r"(r0), "=r"(r1), "=r"(r2), "=r"(r3) : "r"(a));
}
__device__ __forceinline__ void mma_bf16(float* c, const uint32_t* a, uint32_t b0, uint32_t b1) {
    asm volatile("mma.sync.aligned.m16n8k16.row.col.f32.bf16.bf16.f32 "
                 "{%0,%1,%2,%3}, {%4,%5,%6,%7}, {%8,%9}, {%0,%1,%2,%3};"
                 : "+f"(c[0]), "+f"(c[1]), "+f"(c[2]), "+f"(c[3])
                 : "r"(a[0]), "r"(a[1]), "r"(a[2]), "r"(a[3]), "r"(b0), "r"(b1));
}
__device__ __forceinline__ void split2(float x, float y, uint32_t& hi, uint32_t& lo) {
    __nv_bfloat162 h = __floats2bfloat162_rn(x, y);
    float rx = x - __bfloat162float(h.x);
    float ry = y - __bfloat162float(h.y);
    __nv_bfloat162 l = __floats2bfloat162_rn(rx, ry);
    hi = *reinterpret_cast<uint32_t*>(&h);
    lo = *reinterpret_cast<uint32_t*>(&l);
}
__device__ __forceinline__ void cp16(uint32_t dst, const char* src) {
    asm volatile("cp.async.cg.shared.global [%0], [%1], 16;" :: "r"(dst), "l"(src));
}

// ================= pre-convert: K,V fp32 -> bf16 hi/lo swizzled tile images =================
__global__ __launch_bounds__(NT, 4)
void conv_kv_kernel(const float* __restrict__ gk, const float* __restrict__ gv) {
    const int t = blockIdx.x, b = blockIdx.y, tid = threadIdx.x;
    char* dst = g_kv + ((size_t)(b * NT64 + t)) * 4 * TILEB;
    const float4* kg = reinterpret_cast<const float4*>(gk + ((size_t)b * S_LEN + t * 64) * DIM);
    const float4* vg = reinterpret_cast<const float4*>(gv + ((size_t)b * S_LEN + t * 64) * DIM);
    #pragma unroll
    for (int i = 0; i < 8; i++) {
        int idx = tid + i * NT;
        int row = idx >> 5, c4 = idx & 31;
        int chunk = c4 >> 1, sub = (c4 & 1) << 3;
        int off = row * 256 + ((chunk ^ (row & 7)) << 4) + sub;
        float4 kv = kg[idx];
        uint32_t h0, l0, h1, l1;
        split2(kv.x, kv.y, h0, l0);
        split2(kv.z, kv.w, h1, l1);
        *reinterpret_cast<uint2*>(dst + off)             = make_uint2(h0, h1);
        *reinterpret_cast<uint2*>(dst + TILEB + off)     = make_uint2(l0, l1);
        float4 vv = vg[idx];
        split2(vv.x, vv.y, h0, l0);
        split2(vv.z, vv.w, h1, l1);
        *reinterpret_cast<uint2*>(dst + 2 * TILEB + off) = make_uint2(h0, h1);
        *reinterpret_cast<uint2*>(dst + 3 * TILEB + off) = make_uint2(l0, l1);
    }
}

// ================= main attention kernel =================
__global__ __launch_bounds__(NT, 2)
void swa_mma_kernel(const float* __restrict__ gq, const int* __restrict__ wptr,
                    float* __restrict__ gout)
{
    extern __shared__ char smc[];
    const uint32_t sb = s2u(smc);
    const int tid = threadIdx.x, lane = tid & 31, wr = tid >> 5;
    const int rg = wr & 3;
    const int nh = wr >> 2;
    const int q0 = blockIdx.x * BQ, b = blockIdx.y;
    const int w = wptr[0];
    const float scale = rsqrtf((float)DIM);

    const int il0 = rg * 16 + (lane >> 2);
    const int gr  = q0 + il0;
    const int hi4 = lane >> 4;
    const int lo7 = lane & 7;
    const int cbl = (lane >> 3) & 1;
    const int rbl = (lane & 7) + ((lane >> 4) << 3);

    // ---- Q -> smem (hi/lo, swizzled), then preload A-hi fragments to regs ----
    {
        const float4* qg = reinterpret_cast<const float4*>(gq + ((size_t)b * S_LEN + q0) * DIM);
        #pragma unroll
        for (int i = 0; i < 8; i++) {
            int idx = tid + i * NT;
            int row = idx >> 5, c4 = idx & 31;
            int chunk = c4 >> 1, sub = (c4 & 1) << 3;
            float4 vv = qg[idx];
            uint32_t h0, l0, h1, l1;
            split2(vv.x * scale, vv.y * scale, h0, l0);
            split2(vv.z * scale, vv.w * scale, h1, l1);
            int off = row * 256 + ((chunk ^ (row & 7)) << 4) + sub;
            *reinterpret_cast<uint2*>(smc + OQH + off) = make_uint2(h0, h1);
            *reinterpret_cast<uint2*>(smc + OQL + off) = make_uint2(l0, l1);
        }
    }
    __syncthreads();
    uint32_t Ah[8][4];
    {
        uint32_t qb = sb + OQH + (uint32_t)((rg * 16 + (lane & 15)) * 256);
        #pragma unroll
        for (int kk = 0; kk < 8; kk++)
            ldm4(qb + (uint32_t)(((2 * kk + hi4) ^ lo7) << 4),
                 Ah[kk][0], Ah[kk][1], Ah[kk][2], Ah[kk][3]);
    }

    int lo = q0 - (w - 1);              if (lo < 0) lo = 0;
    int hi = q0 + BQ - 1 + (w - 1);     if (hi > S_LEN - 1) hi = S_LEN - 1;
    const int t0 = lo >> 6, t1 = hi >> 6;

    float o[8][4];
    #pragma unroll
    for (int n = 0; n < 8; n++)
        #pragma unroll
        for (int e = 0; e < 4; e++) o[n][e] = 0.f;
    float rs0 = 0.f, rs1 = 0.f;

    for (int t = t0; t <= t1; t++) {
        __syncthreads();                         // prev tile fully consumed
        // ---- cp.async K (group 1), V (group 0) straight into swizzled images ----
        {
            const char* src = g_kv + ((size_t)(b * NT64 + t)) * 4 * TILEB;
            #pragma unroll
            for (int i = 0; i < 8; i++) {
                int off = tid * 16 + i * 4096;
                cp16(sb + OKH + off, src + off);
            }
            asm volatile("cp.async.commit_group;");
            #pragma unroll
            for (int i = 0; i < 8; i++) {
                int off = tid * 16 + i * 4096;
                cp16(sb + OVH + off, src + 2 * TILEB + off);
            }
            asm volatile("cp.async.commit_group;");
        }
        asm volatile("cp.async.wait_group 1;");  // K arrived (thread-local)
        __syncthreads();                         // K visible CTA-wide

        const int k0 = t << 6;
        const int rlo = q0 + rg * 16, rhi = rlo + 15;
        bool skq[2], skp[4];
        #pragma unroll
        for (int np2 = 0; np2 < 2; np2++) {
            int kb0 = k0 + nh * 32 + np2 * 16;
            skq[np2] = (kb0 - rhi >= w) || (rlo - (kb0 + 15) >= w);
        }
        #pragma unroll
        for (int kk2 = 0; kk2 < 4; kk2++) {
            int kb0 = k0 + kk2 * 16;
            skp[kk2] = (kb0 - rhi >= w) || (rlo - (kb0 + 15) >= w);
        }

        // ================= S = Q K^T (bf16x3: Ah*Kh, Ah*Kl, Al*Kh) =================
        float c[4][4];
        #pragma unroll
        for (int n = 0; n < 4; n++)
            #pragma unroll
            for (int e = 0; e < 4; e++) c[n][e] = 0.f;

        #pragma unroll
        for (int pass = 0; pass < 2; pass++) {   // Ah x {Kh, Kl}
            const uint32_t kb = sb + (pass ? (OKH + TILEB) : OKH);
            #pragma unroll
            for (int kk = 0; kk < 8; kk++) {
                #pragma unroll
                for (int np2 = 0; np2 < 2; np2++) {
                    if (!skq[np2]) {
                        uint32_t addr = kb + (uint32_t)(((nh * 2 + np2) * 16 + rbl) * 256
                                      + (((2 * kk + cbl) ^ lo7) << 4));
                        uint32_t b0, b1, b2, b3;
                        ldm4(addr, b0, b1, b2, b3);
                        mma_bf16(c[np2 * 2],     Ah[kk], b0, b1);
                        mma_bf16(c[np2 * 2 + 1], Ah[kk], b2, b3);
                    }
                }
            }
        }
        {                                        // Al x Kh
            const uint32_t qb = sb + OQL + (uint32_t)((rg * 16 + (lane & 15)) * 256);
            #pragma unroll
            for (int kk = 0; kk < 8; kk++) {
                uint32_t Al[4];
                ldm4(qb + (uint32_t)(((2 * kk + hi4) ^ lo7) << 4), Al[0], Al[1], Al[2], Al[3]);
                #pragma unroll
                for (int np2 = 0; np2 < 2; np2++) {
                    if (!skq[np2]) {
                        uint32_t addr = sb + OKH + (uint32_t)(((nh * 2 + np2) * 16 + rbl) * 256
                                      + (((2 * kk + cbl) ^ lo7) << 4));
                        uint32_t b0, b1, b2, b3;
                        ldm4(addr, b0, b1, b2, b3);
                        mma_bf16(c[np2 * 2],     Al, b0, b1);
                        mma_bf16(c[np2 * 2 + 1], Al, b2, b3);
                    }
                }
            }
        }

        // ================= mask + exp + partial rowsum =================
        float ps0 = 0.f, ps1 = 0.f;
        #pragma unroll
        for (int j = 0; j < 4; j++) {
            int jg = k0 + nh * 32 + j * 8 + ((lane & 3) << 1);
            int d0 = gr - jg;
            float e;
            e = (d0 < w && d0 > -w)         ? __expf(c[j][0]) : 0.f; c[j][0] = e; ps0 += e;
            e = (d0 - 1 < w && d0 - 1 > -w) ? __expf(c[j][1]) : 0.f; c[j][1] = e; ps0 += e;
            e = (d0 + 8 < w && d0 + 8 > -w) ? __expf(c[j][2]) : 0.f; c[j][2] = e; ps1 += e;
            e = (d0 + 7 < w && d0 + 7 > -w) ? __expf(c[j][3]) : 0.f; c[j][3] = e; ps1 += e;
        }
        ps0 += __shfl_xor_sync(0xffffffffu, ps0, 1);
        ps0 += __shfl_xor_sync(0xffffffffu, ps0, 2);
        ps1 += __shfl_xor_sync(0xffffffffu, ps1, 1);
        ps1 += __shfl_xor_sync(0xffffffffu, ps1, 2);
        rs0 += ps0; rs1 += ps1;

        // ================= P -> smem (bf16 hi/lo) =================
        asm volatile("cp.async.wait_group 0;");  // V arrived (thread-local)
        #pragma unroll
        for (int j = 0; j < 4; j++) {
            uint32_t h, l;
            int off0 = il0 * 128 + (((nh * 4 + j) ^ (il0 & 7)) << 4) + ((lane & 3) << 2);
            split2(c[j][0], c[j][1], h, l);
            *reinterpret_cast<uint32_t*>(smc + OPH + off0) = h;
            *reinterpret_cast<uint32_t*>(smc + OPL + off0) = l;
            int r1 = il0 + 8;
            int off1 = r1 * 128 + (((nh * 4 + j) ^ (r1 & 7)) << 4) + ((lane & 3) << 2);
            split2(c[j][2], c[j][3], h, l);
            *reinterpret_cast<uint32_t*>(smc + OPH + off1) = h;
            *reinterpret_cast<uint32_t*>(smc + OPL + off1) = l;
        }
        __syncthreads();                         // P + V visible CTA-wide

        // ================= O += P V (each V frag LDSM'd once) =================
        #pragma unroll
        for (int kk2 = 0; kk2 < 4; kk2++) {
            if (!skp[kk2]) {
                uint32_t poff = (uint32_t)((rg * 16 + (lane & 15)) * 128
                              + (((2 * kk2 + hi4) ^ lo7) << 4));
                uint32_t ph[4], pl[4];
                ldm4(sb + OPH + poff, ph[0], ph[1], ph[2], ph[3]);
                ldm4(sb + OPL + poff, pl[0], pl[1], pl[2], pl[3]);
                uint32_t vrow = (uint32_t)((kk2 * 16 + (lane & 15)) * 256);
                #pragma unroll
                for (int vp2 = 0; vp2 < 4; vp2++) {
                    uint32_t voff = vrow + (uint32_t)(((nh * 8 + 2 * vp2 + hi4) ^ lo7) << 4);
                    uint32_t b0, b1, b2, b3;
                    ldm4t(sb + OVH + voff, b0, b1, b2, b3);        // Vh: ph + pl
                    mma_bf16(o[vp2 * 2],     ph, b0, b1);
                    mma_bf16(o[vp2 * 2 + 1], ph, b2, b3);
                    mma_bf16(o[vp2 * 2],     pl, b0, b1);
                    mma_bf16(o[vp2 * 2 + 1], pl, b2, b3);
                    ldm4t(sb + OVL + voff, b0, b1, b2, b3);        // Vl: ph only
                    mma_bf16(o[vp2 * 2],     ph, b0, b1);
                    mma_bf16(o[vp2 * 2 + 1], ph, b2, b3);
                }
            }
        }
    }

    // ================= rowsum combine + normalize + store =================
    __syncthreads();
    float* rsb = reinterpret_cast<float*>(smc + ORS);
    if ((lane & 3) == 0) {
        rsb[nh * 64 + il0]     = rs0;
        rsb[nh * 64 + il0 + 8] = rs1;
    }
    __syncthreads();
    const float inv0 = 1.0f / (rsb[il0]     + rsb[64 + il0]);
    const float inv1 = 1.0f / (rsb[il0 + 8] + rsb[64 + il0 + 8]);

    float* stg = reinterpret_cast<float*>(smc + OSTG);
    const int jd = (lane & 3) << 1;
    #pragma unroll
    for (int n = 0; n < 8; n++) {
        int col = nh * 64 + n * 8 + jd;
        *reinterpret_cast<float2*>(&stg[il0 * 132 + col]) =
            make_float2(o[n][0] * inv0, o[n][1] * inv0);
        *reinterpret_cast<float2*>(&stg[(il0 + 8) * 132 + col]) =
            make_float2(o[n][2] * inv1, o[n][3] * inv1);
    }
    __syncthreads();
    float4* og = reinterpret_cast<float4*>(gout + ((size_t)b * S_LEN + q0) * DIM);
    #pragma unroll
    for (int i = 0; i < 8; i++) {
        int idx = tid + i * NT;
        int row = idx >> 5, c4 = idx & 31;
        og[idx] = *reinterpret_cast<float4*>(&stg[row * 132 + c4 * 4]);
    }
}

extern "C" void kernel_launch(void* const* d_in, const int* in_sizes, int n_in,
                              void* d_out, int out_size) {
    const float* q = (const float*)d_in[0];
    const float* k = (const float*)d_in[1];
    const float* v = (const float*)d_in[2];
    const int*   w = (const int*)d_in[3];
    const int B = in_sizes[0] / (S_LEN * DIM);
    float* out = (float*)d_out;

    conv_kv_kernel<<<dim3(NT64, B), NT>>>(k, v);

    cudaFuncSetAttribute(swa_mma_kernel, cudaFuncAttributeMaxDynamicSharedMemorySize, SMEM_BYTES);
    dim3 grid(S_LEN / BQ, B);
    swa_mma_kernel<<<grid, NT, SMEM_BYTES>>>(q, w, out);
}

// round 7
// speedup vs baseline: 1.3694x; 1.3694x over previous
#include <cuda_runtime.h>
#include <cuda_bf16.h>
#include <cstdint>
#include <math.h>

#define S_LEN 4096
#define DIM   128
#define BQ    64
#define BK    64
#define NT    256
#define NT64  (S_LEN / 64)
#define TILEB 16384

// K/V pre-converted scratch: [B][tile][Kh,Kl,Vh,Vl][16KB] = 16MB
__device__ __align__(16) char g_kv[4 * NT64 * 4 * TILEB];

// per-CTA smem byte offsets (64-row tiles, 256B/row bf16 except P: 128B/row)
#define OQH 0
#define OQL 16384
#define OKH 32768            // Kh,Kl,Vh,Vl contiguous 64KB image
#define OVH 65536
#define OVL 81920
#define OPH 98304
#define OPL 106496
#define SMEM_BYTES 114688
#define ORS OKH
#define OSTG (OKH + 1024)

__device__ __forceinline__ uint32_t s2u(const void* p) {
    uint32_t a;
    asm("{ .reg .u64 t; cvta.to.shared.u64 t, %1; cvt.u32.u64 %0, t; }" : "=r"(a) : "l"(p));
    return a;
}
__device__ __forceinline__ void ldm4(uint32_t a, uint32_t& r0, uint32_t& r1, uint32_t& r2, uint32_t& r3) {
    asm volatile("ldmatrix.sync.aligned.m8n8.x4.shared.b16 {%0,%1,%2,%3}, [%4];"
                 : "=r"(r0), "=r"(r1), "=r"(r2), "=r"(r3) : "r"(a));
}
__device__ __forceinline__ void ldm4t(uint32_t a, uint32_t& r0, uint32_t& r1, uint32_t& r2, uint32_t& r3) {
    asm volatile("ldmatrix.sync.aligned.m8n8.x4.trans.shared.b16 {%0,%1,%2,%3}, [%4];"
                 : "=r"(r0), "=r"(r1), "=r"(r2), "=r"(r3) : "r"(a));
}
__device__ __forceinline__ void mma_bf16(float* c, const uint32_t* a, uint32_t b0, uint32_t b1) {
    asm volatile("mma.sync.aligned.m16n8k16.row.col.f32.bf16.bf16.f32 "
                 "{%0,%1,%2,%3}, {%4,%5,%6,%7}, {%8,%9}, {%0,%1,%2,%3};"
                 : "+f"(c[0]), "+f"(c[1]), "+f"(c[2]), "+f"(c[3])
                 : "r"(a[0]), "r"(a[1]), "r"(a[2]), "r"(a[3]), "r"(b0), "r"(b1));
}
__device__ __forceinline__ void split2(float x, float y, uint32_t& hi, uint32_t& lo) {
    __nv_bfloat162 h = __floats2bfloat162_rn(x, y);
    float rx = x - __bfloat162float(h.x);
    float ry = y - __bfloat162float(h.y);
    __nv_bfloat162 l = __floats2bfloat162_rn(rx, ry);
    hi = *reinterpret_cast<uint32_t*>(&h);
    lo = *reinterpret_cast<uint32_t*>(&l);
}
__device__ __forceinline__ float ex2(float x) {
    float r;
    asm("ex2.approx.f32 %0, %1;" : "=f"(r) : "f"(x));
    return r;
}

// ================= pre-convert: K,V fp32 -> bf16 hi/lo swizzled tile images =================
__global__ __launch_bounds__(NT, 4)
void conv_kv_kernel(const float* __restrict__ gk, const float* __restrict__ gv) {
    const int t = blockIdx.x, b = blockIdx.y, tid = threadIdx.x;
    char* dst = g_kv + ((size_t)(b * NT64 + t)) * 4 * TILEB;
    const float4* kg = reinterpret_cast<const float4*>(gk + ((size_t)b * S_LEN + t * 64) * DIM);
    const float4* vg = reinterpret_cast<const float4*>(gv + ((size_t)b * S_LEN + t * 64) * DIM);
    #pragma unroll
    for (int i = 0; i < 8; i++) {
        int idx = tid + i * NT;
        int row = idx >> 5, c4 = idx & 31;
        int chunk = c4 >> 1, sub = (c4 & 1) << 3;
        int off = row * 256 + ((chunk ^ (row & 7)) << 4) + sub;
        float4 kv = kg[idx];
        uint32_t h0, l0, h1, l1;
        split2(kv.x, kv.y, h0, l0);
        split2(kv.z, kv.w, h1, l1);
        *reinterpret_cast<uint2*>(dst + off)             = make_uint2(h0, h1);
        *reinterpret_cast<uint2*>(dst + TILEB + off)     = make_uint2(l0, l1);
        float4 vv = vg[idx];
        split2(vv.x, vv.y, h0, l0);
        split2(vv.z, vv.w, h1, l1);
        *reinterpret_cast<uint2*>(dst + 2 * TILEB + off) = make_uint2(h0, h1);
        *reinterpret_cast<uint2*>(dst + 3 * TILEB + off) = make_uint2(l0, l1);
    }
}

// ================= main attention kernel =================
__global__ __launch_bounds__(NT, 2)
void swa_mma_kernel(const float* __restrict__ gq, const int* __restrict__ wptr,
                    float* __restrict__ gout)
{
    extern __shared__ char smc[];
    const uint32_t sb = s2u(smc);
    const int tid = threadIdx.x, lane = tid & 31, wr = tid >> 5;
    const int rg = wr & 3;            // row group: rows rg*16..+15
    const int nh = wr >> 2;           // key-half (QK) / output-col-half (PV)
    const int q0 = blockIdx.x * BQ, b = blockIdx.y;
    const int w = wptr[0];
    const float scale = 1.44269504f * rsqrtf((float)DIM);   // fold log2e: exp(s)=exp2(s')

    const int il0 = rg * 16 + (lane >> 2);
    const int gr  = q0 + il0;
    const int hi4 = lane >> 4;
    const int lo7 = lane & 7;
    const int cbl = (lane >> 3) & 1;
    const int rbl = (lane & 7) + ((lane >> 4) << 3);

    // ---- Q -> smem (hi/lo, swizzled), inline conversion (once) ----
    {
        const float4* qg = reinterpret_cast<const float4*>(gq + ((size_t)b * S_LEN + q0) * DIM);
        #pragma unroll
        for (int i = 0; i < 8; i++) {
            int idx = tid + i * NT;
            int row = idx >> 5, c4 = idx & 31;
            int chunk = c4 >> 1, sub = (c4 & 1) << 3;
            float4 vv = qg[idx];
            uint32_t h0, l0, h1, l1;
            split2(vv.x * scale, vv.y * scale, h0, l0);
            split2(vv.z * scale, vv.w * scale, h1, l1);
            int off = row * 256 + ((chunk ^ (row & 7)) << 4) + sub;
            *reinterpret_cast<uint2*>(smc + OQH + off) = make_uint2(h0, h1);
            *reinterpret_cast<uint2*>(smc + OQL + off) = make_uint2(l0, l1);
        }
    }

    int lo = q0 - (w - 1);              if (lo < 0) lo = 0;
    int hi = q0 + BQ - 1 + (w - 1);     if (hi > S_LEN - 1) hi = S_LEN - 1;
    const int t0 = lo >> 6, t1 = hi >> 6;

    float o[8][4];
    #pragma unroll
    for (int n = 0; n < 8; n++)
        #pragma unroll
        for (int e = 0; e < 4; e++) o[n][e] = 0.f;
    float rs0 = 0.f, rs1 = 0.f;

    for (int t = t0; t <= t1; t++) {
        __syncthreads();                     // prev tile fully consumed (also covers Q store 1st iter)
        // ---- copy pre-converted Kh,Kl,Vh,Vl (64KB) into smem image ----
        {
            const char* src = g_kv + ((size_t)(b * NT64 + t)) * 4 * TILEB;
            #pragma unroll
            for (int i = 0; i < 16; i++) {
                int off = tid * 16 + i * 4096;
                *reinterpret_cast<uint4*>(smc + OKH + off) =
                    *reinterpret_cast<const uint4*>(src + off);
            }
        }
        __syncthreads();

        const int k0 = t << 6;
        const int rlo = q0 + rg * 16, rhi = rlo + 15;
        bool skq[2], skp[4];
        #pragma unroll
        for (int np2 = 0; np2 < 2; np2++) {
            int kb0 = k0 + nh * 32 + np2 * 16;
            skq[np2] = (kb0 - rhi >= w) || (rlo - (kb0 + 15) >= w);
        }
        #pragma unroll
        for (int kk2 = 0; kk2 < 4; kk2++) {
            int kb0 = k0 + kk2 * 16;
            skp[kk2] = (kb0 - rhi >= w) || (rlo - (kb0 + 15) >= w);
        }

        // ================= S = Q K^T (bf16x3) =================
        float c[4][4];
        #pragma unroll
        for (int n = 0; n < 4; n++)
            #pragma unroll
            for (int e = 0; e < 4; e++) c[n][e] = 0.f;

        uint32_t A[8][4];
        #pragma unroll
        for (int pass = 0; pass < 3; pass++) {
            if (pass != 1) {
                uint32_t qb = sb + (pass ? OQL : OQH)
                            + (uint32_t)((rg * 16 + (lane & 15)) * 256);
                #pragma unroll
                for (int kk = 0; kk < 8; kk++)
                    ldm4(qb + (uint32_t)(((2 * kk + hi4) ^ lo7) << 4),
                         A[kk][0], A[kk][1], A[kk][2], A[kk][3]);
            }
            const uint32_t kb = sb + ((pass == 1) ? (OKH + TILEB) : OKH);
            #pragma unroll
            for (int kk = 0; kk < 8; kk++) {
                #pragma unroll
                for (int np2 = 0; np2 < 2; np2++) {
                    if (!skq[np2]) {
                        uint32_t addr = kb + (uint32_t)(((nh * 2 + np2) * 16 + rbl) * 256
                                      + (((2 * kk + cbl) ^ lo7) << 4));
                        uint32_t b0, b1, b2, b3;
                        ldm4(addr, b0, b1, b2, b3);
                        mma_bf16(c[np2 * 2],     A[kk], b0, b1);
                        mma_bf16(c[np2 * 2 + 1], A[kk], b2, b3);
                    }
                }
            }
        }

        // ================= mask + exp2 + partial rowsum =================
        float ps0 = 0.f, ps1 = 0.f;
        #pragma unroll
        for (int j = 0; j < 4; j++) {
            int jg = k0 + nh * 32 + j * 8 + ((lane & 3) << 1);
            int d0 = gr - jg;
            float e;
            e = (d0 < w && d0 > -w)         ? ex2(c[j][0]) : 0.f; c[j][0] = e; ps0 += e;
            e = (d0 - 1 < w && d0 - 1 > -w) ? ex2(c[j][1]) : 0.f; c[j][1] = e; ps0 += e;
            e = (d0 + 8 < w && d0 + 8 > -w) ? ex2(c[j][2]) : 0.f; c[j][2] = e; ps1 += e;
            e = (d0 + 7 < w && d0 + 7 > -w) ? ex2(c[j][3]) : 0.f; c[j][3] = e; ps1 += e;
        }
        ps0 += __shfl_xor_sync(0xffffffffu, ps0, 1);
        ps0 += __shfl_xor_sync(0xffffffffu, ps0, 2);
        ps1 += __shfl_xor_sync(0xffffffffu, ps1, 1);
        ps1 += __shfl_xor_sync(0xffffffffu, ps1, 2);
        rs0 += ps0; rs1 += ps1;

        // ================= P -> smem (bf16 hi/lo) =================
        #pragma unroll
        for (int j = 0; j < 4; j++) {
            uint32_t h, l;
            int off0 = il0 * 128 + (((nh * 4 + j) ^ (il0 & 7)) << 4) + ((lane & 3) << 2);
            split2(c[j][0], c[j][1], h, l);
            *reinterpret_cast<uint32_t*>(smc + OPH + off0) = h;
            *reinterpret_cast<uint32_t*>(smc + OPL + off0) = l;
            int r1 = il0 + 8;
            int off1 = r1 * 128 + (((nh * 4 + j) ^ (r1 & 7)) << 4) + ((lane & 3) << 2);
            split2(c[j][2], c[j][3], h, l);
            *reinterpret_cast<uint32_t*>(smc + OPH + off1) = h;
            *reinterpret_cast<uint32_t*>(smc + OPL + off1) = l;
        }
        __syncthreads();                     // P visible to partner warps

        // ================= O += P V (bf16x3, R5 form) =================
        #pragma unroll
        for (int pass = 0; pass < 3; pass++) {
            const uint32_t pb = sb + ((pass == 2) ? OPL : OPH);
            const uint32_t vb = sb + ((pass == 1) ? OVL : OVH);
            #pragma unroll
            for (int kk2 = 0; kk2 < 4; kk2++) {
                if (!skp[kk2]) {
                    uint32_t a0, a1, a2, a3;
                    ldm4(pb + (uint32_t)((rg * 16 + (lane & 15)) * 128
                             + (((2 * kk2 + hi4) ^ lo7) << 4)), a0, a1, a2, a3);
                    uint32_t Af[4] = {a0, a1, a2, a3};
                    uint32_t vrow = vb + (uint32_t)((kk2 * 16 + (lane & 15)) * 256);
                    #pragma unroll
                    for (int vp2 = 0; vp2 < 4; vp2++) {
                        uint32_t b0, b1, b2, b3;
                        ldm4t(vrow + (uint32_t)(((nh * 8 + 2 * vp2 + hi4) ^ lo7) << 4),
                              b0, b1, b2, b3);
                        mma_bf16(o[vp2 * 2],     Af, b0, b1);
                        mma_bf16(o[vp2 * 2 + 1], Af, b2, b3);
                    }
                }
            }
        }
    }

    // ================= rowsum combine + normalize + store =================
    __syncthreads();
    float* rsb = reinterpret_cast<float*>(smc + ORS);
    if ((lane & 3) == 0) {
        rsb[nh * 64 + il0]     = rs0;
        rsb[nh * 64 + il0 + 8] = rs1;
    }
    __syncthreads();
    const float inv0 = 1.0f / (rsb[il0]     + rsb[64 + il0]);
    const float inv1 = 1.0f / (rsb[il0 + 8] + rsb[64 + il0 + 8]);

    float* stg = reinterpret_cast<float*>(smc + OSTG);
    const int jd = (lane & 3) << 1;
    #pragma unroll
    for (int n = 0; n < 8; n++) {
        int col = nh * 64 + n * 8 + jd;
        *reinterpret_cast<float2*>(&stg[il0 * 132 + col]) =
            make_float2(o[n][0] * inv0, o[n][1] * inv0);
        *reinterpret_cast<float2*>(&stg[(il0 + 8) * 132 + col]) =
            make_float2(o[n][2] * inv1, o[n][3] * inv1);
    }
    __syncthreads();
    float4* og = reinterpret_cast<float4*>(gout + ((size_t)b * S_LEN + q0) * DIM);
    #pragma unroll
    for (int i = 0; i < 8; i++) {
        int idx = tid + i * NT;
        int row = idx >> 5, c4 = idx & 31;
        og[idx] = *reinterpret_cast<float4*>(&stg[row * 132 + c4 * 4]);
    }
}

extern "C" void kernel_launch(void* const* d_in, const int* in_sizes, int n_in,
                              void* d_out, int out_size) {
    const float* q = (const float*)d_in[0];
    const float* k = (const float*)d_in[1];
    const float* v = (const float*)d_in[2];
    const int*   w = (const int*)d_in[3];
    const int B = in_sizes[0] / (S_LEN * DIM);
    float* out = (float*)d_out;

    conv_kv_kernel<<<dim3(NT64, B), NT>>>(k, v);

    cudaFuncSetAttribute(swa_mma_kernel, cudaFuncAttributeMaxDynamicSharedMemorySize, SMEM_BYTES);
    dim3 grid(S_LEN / BQ, B);
    swa_mma_kernel<<<grid, NT, SMEM_BYTES>>>(q, w, out);
}

// round 8
// speedup vs baseline: 1.5020x; 1.0969x over previous
#include <cuda_runtime.h>
#include <cuda_bf16.h>
#include <cstdint>
#include <math.h>

#define S_LEN 4096
#define DIM   128
#define BQ    64
#define BK    64
#define NT    256
#define NT64  (S_LEN / 64)
#define TILEB 16384

// K/V pre-converted scratch: [B][tile][Kh,Kl,Vh,Vl][16KB] = 16MB
__device__ __align__(16) char g_kv[4 * NT64 * 4 * TILEB];

// per-CTA smem byte offsets
#define OQH 0
#define OQL 16384
#define OKH 32768            // Kh(16K)+Kl(16K)
#define OVH 65536            // Vh(16K)+Vl(16K)
#define OVL 81920
#define OPH 98304
#define OPL 106496
#define SMEM_BYTES 114688
#define ORS OKH
#define OSTG (OKH + 1024)

__device__ __forceinline__ uint32_t s2u(const void* p) {
    uint32_t a;
    asm("{ .reg .u64 t; cvta.to.shared.u64 t, %1; cvt.u32.u64 %0, t; }" : "=r"(a) : "l"(p));
    return a;
}
__device__ __forceinline__ void ldm4(uint32_t a, uint32_t& r0, uint32_t& r1, uint32_t& r2, uint32_t& r3) {
    asm volatile("ldmatrix.sync.aligned.m8n8.x4.shared.b16 {%0,%1,%2,%3}, [%4];"
                 : "=r"(r0), "=r"(r1), "=r"(r2), "=r"(r3) : "r"(a));
}
__device__ __forceinline__ void ldm4t(uint32_t a, uint32_t& r0, uint32_t& r1, uint32_t& r2, uint32_t& r3) {
    asm volatile("ldmatrix.sync.aligned.m8n8.x4.trans.shared.b16 {%0,%1,%2,%3}, [%4];"
                 : "=r"(r0), "=r"(r1), "=r"(r2), "=r"(r3) : "r"(a));
}
__device__ __forceinline__ void mma_bf16(float* c, const uint32_t* a, uint32_t b0, uint32_t b1) {
    asm volatile("mma.sync.aligned.m16n8k16.row.col.f32.bf16.bf16.f32 "
                 "{%0,%1,%2,%3}, {%4,%5,%6,%7}, {%8,%9}, {%0,%1,%2,%3};"
                 : "+f"(c[0]), "+f"(c[1]), "+f"(c[2]), "+f"(c[3])
                 : "r"(a[0]), "r"(a[1]), "r"(a[2]), "r"(a[3]), "r"(b0), "r"(b1));
}
__device__ __forceinline__ void split2(float x, float y, uint32_t& hi, uint32_t& lo) {
    __nv_bfloat162 h = __floats2bfloat162_rn(x, y);
    float rx = x - __bfloat162float(h.x);
    float ry = y - __bfloat162float(h.y);
    __nv_bfloat162 l = __floats2bfloat162_rn(rx, ry);
    hi = *reinterpret_cast<uint32_t*>(&h);
    lo = *reinterpret_cast<uint32_t*>(&l);
}
__device__ __forceinline__ float ex2(float x) {
    float r;
    asm("ex2.approx.f32 %0, %1;" : "=f"(r) : "f"(x));
    return r;
}
__device__ __forceinline__ void cp16(uint32_t dst, const char* src) {
    asm volatile("cp.async.cg.shared.global [%0], [%1], 16;" :: "r"(dst), "l"(src));
}
#define CP_COMMIT() asm volatile("cp.async.commit_group;")
#define CP_WAIT1()  asm volatile("cp.async.wait_group 1;")
#define CP_WAIT0()  asm volatile("cp.async.wait_group 0;")

// ================= pre-convert: K,V fp32 -> bf16 hi/lo swizzled tile images =================
__global__ __launch_bounds__(NT, 4)
void conv_kv_kernel(const float* __restrict__ gk, const float* __restrict__ gv) {
    const int t = blockIdx.x, b = blockIdx.y, tid = threadIdx.x;
    char* dst = g_kv + ((size_t)(b * NT64 + t)) * 4 * TILEB;
    const float4* kg = reinterpret_cast<const float4*>(gk + ((size_t)b * S_LEN + t * 64) * DIM);
    const float4* vg = reinterpret_cast<const float4*>(gv + ((size_t)b * S_LEN + t * 64) * DIM);
    #pragma unroll
    for (int i = 0; i < 8; i++) {
        int idx = tid + i * NT;
        int row = idx >> 5, c4 = idx & 31;
        int chunk = c4 >> 1, sub = (c4 & 1) << 3;
        int off = row * 256 + ((chunk ^ (row & 7)) << 4) + sub;
        float4 kv = kg[idx];
        uint32_t h0, l0, h1, l1;
        split2(kv.x, kv.y, h0, l0);
        split2(kv.z, kv.w, h1, l1);
        *reinterpret_cast<uint2*>(dst + off)             = make_uint2(h0, h1);
        *reinterpret_cast<uint2*>(dst + TILEB + off)     = make_uint2(l0, l1);
        float4 vv = vg[idx];
        split2(vv.x, vv.y, h0, l0);
        split2(vv.z, vv.w, h1, l1);
        *reinterpret_cast<uint2*>(dst + 2 * TILEB + off) = make_uint2(h0, h1);
        *reinterpret_cast<uint2*>(dst + 3 * TILEB + off) = make_uint2(l0, l1);
    }
}

// ================= main attention kernel =================
__global__ __launch_bounds__(NT, 2)
void swa_mma_kernel(const float* __restrict__ gq, const int* __restrict__ wptr,
                    float* __restrict__ gout)
{
    extern __shared__ char smc[];
    const uint32_t sb = s2u(smc);
    const int tid = threadIdx.x, lane = tid & 31, wr = tid >> 5;
    const int rg = wr & 3;
    const int nh = wr >> 2;
    const int q0 = blockIdx.x * BQ, b = blockIdx.y;
    const int w = wptr[0];
    const float scale = 1.44269504f * rsqrtf((float)DIM);

    const int il0 = rg * 16 + (lane >> 2);
    const int gr  = q0 + il0;
    const int hi4 = lane >> 4;
    const int lo7 = lane & 7;
    const int cbl = (lane >> 3) & 1;
    const int rbl = (lane & 7) + ((lane >> 4) << 3);

    int lo = q0 - (w - 1);              if (lo < 0) lo = 0;
    int hi = q0 + BQ - 1 + (w - 1);     if (hi > S_LEN - 1) hi = S_LEN - 1;
    const int t0 = lo >> 6, t1 = hi >> 6;

    const char* kvbase = g_kv + ((size_t)b * NT64) * 4 * TILEB;

    // ---- prologue: async copies for tile t0 (K group, then V group) ----
    {
        const char* src = kvbase + (size_t)t0 * 4 * TILEB;
        #pragma unroll
        for (int i = 0; i < 8; i++) {
            int off = tid * 16 + i * 4096;
            cp16(sb + OKH + off, src + off);
        }
        CP_COMMIT();
        #pragma unroll
        for (int i = 0; i < 8; i++) {
            int off = tid * 16 + i * 4096;
            cp16(sb + OVH + off, src + 2 * TILEB + off);
        }
        CP_COMMIT();
    }

    // ---- Q -> smem (hi/lo, swizzled) — overlaps the prologue copies ----
    {
        const float4* qg = reinterpret_cast<const float4*>(gq + ((size_t)b * S_LEN + q0) * DIM);
        #pragma unroll
        for (int i = 0; i < 8; i++) {
            int idx = tid + i * NT;
            int row = idx >> 5, c4 = idx & 31;
            int chunk = c4 >> 1, sub = (c4 & 1) << 3;
            float4 vv = qg[idx];
            uint32_t h0, l0, h1, l1;
            split2(vv.x * scale, vv.y * scale, h0, l0);
            split2(vv.z * scale, vv.w * scale, h1, l1);
            int off = row * 256 + ((chunk ^ (row & 7)) << 4) + sub;
            *reinterpret_cast<uint2*>(smc + OQH + off) = make_uint2(h0, h1);
            *reinterpret_cast<uint2*>(smc + OQL + off) = make_uint2(l0, l1);
        }
    }

    float o[8][4];
    #pragma unroll
    for (int n = 0; n < 8; n++)
        #pragma unroll
        for (int e = 0; e < 4; e++) o[n][e] = 0.f;
    float rs0 = 0.f, rs1 = 0.f;

    for (int t = t0; t <= t1; t++) {
        const int k0 = t << 6;
        const int rlo = q0 + rg * 16, rhi = rlo + 15;
        bool skq[2], skp[4];
        #pragma unroll
        for (int np2 = 0; np2 < 2; np2++) {
            int kb0 = k0 + nh * 32 + np2 * 16;
            skq[np2] = (kb0 - rhi >= w) || (rlo - (kb0 + 15) >= w);
        }
        #pragma unroll
        for (int kk2 = 0; kk2 < 4; kk2++) {
            int kb0 = k0 + kk2 * 16;
            skp[kk2] = (kb0 - rhi >= w) || (rlo - (kb0 + 15) >= w);
        }

        CP_WAIT1();                // K(t) arrived (V(t) may still be in flight)
        __syncthreads();           // K visible CTA-wide (also: Q visible on 1st iter,
                                   //  prev P/V consumed on later iters)

        // ================= S = Q K^T (bf16x3) =================
        float c[4][4];
        #pragma unroll
        for (int n = 0; n < 4; n++)
            #pragma unroll
            for (int e = 0; e < 4; e++) c[n][e] = 0.f;

        uint32_t A[8][4];
        #pragma unroll
        for (int pass = 0; pass < 3; pass++) {
            if (pass != 1) {
                uint32_t qb = sb + (pass ? OQL : OQH)
                            + (uint32_t)((rg * 16 + (lane & 15)) * 256);
                #pragma unroll
                for (int kk = 0; kk < 8; kk++)
                    ldm4(qb + (uint32_t)(((2 * kk + hi4) ^ lo7) << 4),
                         A[kk][0], A[kk][1], A[kk][2], A[kk][3]);
            }
            const uint32_t kb = sb + ((pass == 1) ? (OKH + TILEB) : OKH);
            #pragma unroll
            for (int kk = 0; kk < 8; kk++) {
                #pragma unroll
                for (int np2 = 0; np2 < 2; np2++) {
                    if (!skq[np2]) {
                        uint32_t addr = kb + (uint32_t)(((nh * 2 + np2) * 16 + rbl) * 256
                                      + (((2 * kk + cbl) ^ lo7) << 4));
                        uint32_t b0, b1, b2, b3;
                        ldm4(addr, b0, b1, b2, b3);
                        mma_bf16(c[np2 * 2],     A[kk], b0, b1);
                        mma_bf16(c[np2 * 2 + 1], A[kk], b2, b3);
                    }
                }
            }
        }

        __syncthreads();           // all warps done reading K(t)
        if (t < t1) {              // prefetch K(t+1): overlaps exp + P store + PV
            const char* src = kvbase + (size_t)(t + 1) * 4 * TILEB;
            #pragma unroll
            for (int i = 0; i < 8; i++) {
                int off = tid * 16 + i * 4096;
                cp16(sb + OKH + off, src + off);
            }
            CP_COMMIT();
        }

        // ================= mask + exp2 + partial rowsum =================
        float ps0 = 0.f, ps1 = 0.f;
        #pragma unroll
        for (int j = 0; j < 4; j++) {
            int jg = k0 + nh * 32 + j * 8 + ((lane & 3) << 1);
            int d0 = gr - jg;
            float e;
            e = (d0 < w && d0 > -w)         ? ex2(c[j][0]) : 0.f; c[j][0] = e; ps0 += e;
            e = (d0 - 1 < w && d0 - 1 > -w) ? ex2(c[j][1]) : 0.f; c[j][1] = e; ps0 += e;
            e = (d0 + 8 < w && d0 + 8 > -w) ? ex2(c[j][2]) : 0.f; c[j][2] = e; ps1 += e;
            e = (d0 + 7 < w && d0 + 7 > -w) ? ex2(c[j][3]) : 0.f; c[j][3] = e; ps1 += e;
        }
        ps0 += __shfl_xor_sync(0xffffffffu, ps0, 1);
        ps0 += __shfl_xor_sync(0xffffffffu, ps0, 2);
        ps1 += __shfl_xor_sync(0xffffffffu, ps1, 1);
        ps1 += __shfl_xor_sync(0xffffffffu, ps1, 2);
        rs0 += ps0; rs1 += ps1;

        // ================= P -> smem (bf16 hi/lo) =================
        #pragma unroll
        for (int j = 0; j < 4; j++) {
            uint32_t h, l;
            int off0 = il0 * 128 + (((nh * 4 + j) ^ (il0 & 7)) << 4) + ((lane & 3) << 2);
            split2(c[j][0], c[j][1], h, l);
            *reinterpret_cast<uint32_t*>(smc + OPH + off0) = h;
            *reinterpret_cast<uint32_t*>(smc + OPL + off0) = l;
            int r1 = il0 + 8;
            int off1 = r1 * 128 + (((nh * 4 + j) ^ (r1 & 7)) << 4) + ((lane & 3) << 2);
            split2(c[j][2], c[j][3], h, l);
            *reinterpret_cast<uint32_t*>(smc + OPH + off1) = h;
            *reinterpret_cast<uint32_t*>(smc + OPL + off1) = l;
        }
        if (t < t1) CP_WAIT1(); else CP_WAIT0();   // V(t) arrived
        __syncthreads();           // P + V visible CTA-wide

        // ================= O += P V (bf16x3) =================
        #pragma unroll
        for (int pass = 0; pass < 3; pass++) {
            const uint32_t pb = sb + ((pass == 2) ? OPL : OPH);
            const uint32_t vb = sb + ((pass == 1) ? OVL : OVH);
            #pragma unroll
            for (int kk2 = 0; kk2 < 4; kk2++) {
                if (!skp[kk2]) {
                    uint32_t a0, a1, a2, a3;
                    ldm4(pb + (uint32_t)((rg * 16 + (lane & 15)) * 128
                             + (((2 * kk2 + hi4) ^ lo7) << 4)), a0, a1, a2, a3);
                    uint32_t Af[4] = {a0, a1, a2, a3};
                    uint32_t vrow = vb + (uint32_t)((kk2 * 16 + (lane & 15)) * 256);
                    #pragma unroll
                    for (int vp2 = 0; vp2 < 4; vp2++) {
                        uint32_t b0, b1, b2, b3;
                        ldm4t(vrow + (uint32_t)(((nh * 8 + 2 * vp2 + hi4) ^ lo7) << 4),
                              b0, b1, b2, b3);
                        mma_bf16(o[vp2 * 2],     Af, b0, b1);
                        mma_bf16(o[vp2 * 2 + 1], Af, b2, b3);
                    }
                }
            }
        }

        __syncthreads();           // V(t) + P consumed
        if (t < t1) {              // prefetch V(t+1): overlaps QK(t+1)
            const char* src = kvbase + (size_t)(t + 1) * 4 * TILEB;
            #pragma unroll
            for (int i = 0; i < 8; i++) {
                int off = tid * 16 + i * 4096;
                cp16(sb + OVH + off, src + 2 * TILEB + off);
            }
            CP_COMMIT();
        }
    }

    // ================= rowsum combine + normalize + store =================
    __syncthreads();
    float* rsb = reinterpret_cast<float*>(smc + ORS);
    if ((lane & 3) == 0) {
        rsb[nh * 64 + il0]     = rs0;
        rsb[nh * 64 + il0 + 8] = rs1;
    }
    __syncthreads();
    const float inv0 = 1.0f / (rsb[il0]     + rsb[64 + il0]);
    const float inv1 = 1.0f / (rsb[il0 + 8] + rsb[64 + il0 + 8]);

    float* stg = reinterpret_cast<float*>(smc + OSTG);
    const int jd = (lane & 3) << 1;
    #pragma unroll
    for (int n = 0; n < 8; n++) {
        int col = nh * 64 + n * 8 + jd;
        *reinterpret_cast<float2*>(&stg[il0 * 132 + col]) =
            make_float2(o[n][0] * inv0, o[n][1] * inv0);
        *reinterpret_cast<float2*>(&stg[(il0 + 8) * 132 + col]) =
            make_float2(o[n][2] * inv1, o[n][3] * inv1);
    }
    __syncthreads();
    float4* og = reinterpret_cast<float4*>(gout + ((size_t)b * S_LEN + q0) * DIM);
    #pragma unroll
    for (int i = 0; i < 8; i++) {
        int idx = tid + i * NT;
        int row = idx >> 5, c4 = idx & 31;
        og[idx] = *reinterpret_cast<float4*>(&stg[row * 132 + c4 * 4]);
    }
}

extern "C" void kernel_launch(void* const* d_in, const int* in_sizes, int n_in,
                              void* d_out, int out_size) {
    const float* q = (const float*)d_in[0];
    const float* k = (const float*)d_in[1];
    const float* v = (const float*)d_in[2];
    const int*   w = (const int*)d_in[3];
    const int B = in_sizes[0] / (S_LEN * DIM);
    float* out = (float*)d_out;

    conv_kv_kernel<<<dim3(NT64, B), NT>>>(k, v);

    cudaFuncSetAttribute(swa_mma_kernel, cudaFuncAttributeMaxDynamicSharedMemorySize, SMEM_BYTES);
    dim3 grid(S_LEN / BQ, B);
    swa_mma_kernel<<<grid, NT, SMEM_BYTES>>>(q, w, out);
}

// round 9
// speedup vs baseline: 1.5785x; 1.0509x over previous
#include <cuda_runtime.h>
#include <cuda_bf16.h>
#include <cstdint>
#include <math.h>

#define S_LEN 4096
#define DIM   128
#define BQ    64
#define BK    64
#define NT    256
#define NT64  (S_LEN / 64)
#define TILEB 16384

// K/V pre-converted scratch: [B][tile][Kh,Kl,Vh,Vl][16KB] = 16MB
__device__ __align__(16) char g_kv[4 * NT64 * 4 * TILEB];

// per-CTA smem byte offsets
#define OQH 0
#define OQL 16384
#define OKH 32768            // Kh(16K)+Kl(16K)
#define OVH 65536            // Vh(16K)+Vl(16K)
#define OVL 81920
#define OPH 98304
#define OPL 106496
#define SMEM_BYTES 114688
#define ORS OKH
#define OSTG (OKH + 1024)

__device__ __forceinline__ uint32_t s2u(const void* p) {
    uint32_t a;
    asm("{ .reg .u64 t; cvta.to.shared.u64 t, %1; cvt.u32.u64 %0, t; }" : "=r"(a) : "l"(p));
    return a;
}
__device__ __forceinline__ void ldm4(uint32_t a, uint32_t& r0, uint32_t& r1, uint32_t& r2, uint32_t& r3) {
    asm volatile("ldmatrix.sync.aligned.m8n8.x4.shared.b16 {%0,%1,%2,%3}, [%4];"
                 : "=r"(r0), "=r"(r1), "=r"(r2), "=r"(r3) : "r"(a));
}
__device__ __forceinline__ void ldm4t(uint32_t a, uint32_t& r0, uint32_t& r1, uint32_t& r2, uint32_t& r3) {
    asm volatile("ldmatrix.sync.aligned.m8n8.x4.trans.shared.b16 {%0,%1,%2,%3}, [%4];"
                 : "=r"(r0), "=r"(r1), "=r"(r2), "=r"(r3) : "r"(a));
}
__device__ __forceinline__ void mma_bf16(float* c, const uint32_t* a, uint32_t b0, uint32_t b1) {
    asm volatile("mma.sync.aligned.m16n8k16.row.col.f32.bf16.bf16.f32 "
                 "{%0,%1,%2,%3}, {%4,%5,%6,%7}, {%8,%9}, {%0,%1,%2,%3};"
                 : "+f"(c[0]), "+f"(c[1]), "+f"(c[2]), "+f"(c[3])
                 : "r"(a[0]), "r"(a[1]), "r"(a[2]), "r"(a[3]), "r"(b0), "r"(b1));
}
__device__ __forceinline__ void split2(float x, float y, uint32_t& hi, uint32_t& lo) {
    __nv_bfloat162 h = __floats2bfloat162_rn(x, y);
    float rx = x - __bfloat162float(h.x);
    float ry = y - __bfloat162float(h.y);
    __nv_bfloat162 l = __floats2bfloat162_rn(rx, ry);
    hi = *reinterpret_cast<uint32_t*>(&h);
    lo = *reinterpret_cast<uint32_t*>(&l);
}
__device__ __forceinline__ float ex2(float x) {
    float r;
    asm("ex2.approx.f32 %0, %1;" : "=f"(r) : "f"(x));
    return r;
}
__device__ __forceinline__ void cp16(uint32_t dst, const char* src) {
    asm volatile("cp.async.cg.shared.global [%0], [%1], 16;" :: "r"(dst), "l"(src));
}
#define CP_COMMIT() asm volatile("cp.async.commit_group;")
#define CP_WAIT0()  asm volatile("cp.async.wait_group 0;")

// ---- one QK bf16 pass: c[0..3] += A(q rows) x B(keys), per-kk A load ----
__device__ __forceinline__ void qk_pass(float (*c)[4], uint32_t qbase, uint32_t kbase,
                                        bool sk0, bool sk1, uint32_t krow0, uint32_t krow1,
                                        int hi4, int lo7, int cbl) {
    #pragma unroll
    for (int kk = 0; kk < 8; kk++) {
        uint32_t A[4];
        ldm4(qbase + (uint32_t)(((2 * kk + hi4) ^ lo7) << 4), A[0], A[1], A[2], A[3]);
        uint32_t kcol = (uint32_t)(((2 * kk + cbl) ^ lo7) << 4);
        if (!sk0) {
            uint32_t b0, b1, b2, b3;
            ldm4(kbase + krow0 + kcol, b0, b1, b2, b3);
            mma_bf16(c[0], A, b0, b1);
            mma_bf16(c[1], A, b2, b3);
        }
        if (!sk1) {
            uint32_t b0, b1, b2, b3;
            ldm4(kbase + krow1 + kcol, b0, b1, b2, b3);
            mma_bf16(c[2], A, b0, b1);
            mma_bf16(c[3], A, b2, b3);
        }
    }
}

// ---- one PV bf16 pass: o += P x V ----
__device__ __forceinline__ void pv_pass(float (*o)[4], uint32_t pbase, uint32_t vbase,
                                        const bool* skp, int hi4, int lo7, int nh) {
    #pragma unroll
    for (int kk2 = 0; kk2 < 4; kk2++) {
        if (!skp[kk2]) {
            uint32_t a0, a1, a2, a3;
            ldm4(pbase + (uint32_t)(((2 * kk2 + hi4) ^ lo7) << 4), a0, a1, a2, a3);
            uint32_t Af[4] = {a0, a1, a2, a3};
            uint32_t vrow = vbase + (uint32_t)(kk2 * 16 * 256);
            #pragma unroll
            for (int vp2 = 0; vp2 < 4; vp2++) {
                uint32_t b0, b1, b2, b3;
                ldm4t(vrow + (uint32_t)(((nh * 8 + 2 * vp2 + hi4) ^ lo7) << 4), b0, b1, b2, b3);
                mma_bf16(o[vp2 * 2],     Af, b0, b1);
                mma_bf16(o[vp2 * 2 + 1], Af, b2, b3);
            }
        }
    }
}

// ================= pre-convert: K,V fp32 -> bf16 hi/lo swizzled tile images =================
__global__ __launch_bounds__(NT, 4)
void conv_kv_kernel(const float* __restrict__ gk, const float* __restrict__ gv) {
    const int t = blockIdx.x, b = blockIdx.y, tid = threadIdx.x;
    char* dst = g_kv + ((size_t)(b * NT64 + t)) * 4 * TILEB;
    const float4* kg = reinterpret_cast<const float4*>(gk + ((size_t)b * S_LEN + t * 64) * DIM);
    const float4* vg = reinterpret_cast<const float4*>(gv + ((size_t)b * S_LEN + t * 64) * DIM);
    #pragma unroll
    for (int i = 0; i < 8; i++) {
        int idx = tid + i * NT;
        int row = idx >> 5, c4 = idx & 31;
        int chunk = c4 >> 1, sub = (c4 & 1) << 3;
        int off = row * 256 + ((chunk ^ (row & 7)) << 4) + sub;
        float4 kv = kg[idx];
        uint32_t h0, l0, h1, l1;
        split2(kv.x, kv.y, h0, l0);
        split2(kv.z, kv.w, h1, l1);
        *reinterpret_cast<uint2*>(dst + off)             = make_uint2(h0, h1);
        *reinterpret_cast<uint2*>(dst + TILEB + off)     = make_uint2(l0, l1);
        float4 vv = vg[idx];
        split2(vv.x, vv.y, h0, l0);
        split2(vv.z, vv.w, h1, l1);
        *reinterpret_cast<uint2*>(dst + 2 * TILEB + off) = make_uint2(h0, h1);
        *reinterpret_cast<uint2*>(dst + 3 * TILEB + off) = make_uint2(l0, l1);
    }
}

// ================= main attention kernel (pipelined: PV(t) fused with QK(t+1)) =================
__global__ __launch_bounds__(NT, 2)
void swa_mma_kernel(const float* __restrict__ gq, const int* __restrict__ wptr,
                    float* __restrict__ gout)
{
    extern __shared__ char smc[];
    const uint32_t sb = s2u(smc);
    const int tid = threadIdx.x, lane = tid & 31, wr = tid >> 5;
    const int rg = wr & 3;
    const int nh = wr >> 2;
    const int q0 = blockIdx.x * BQ, b = blockIdx.y;
    const int w = wptr[0];
    const float scale = 1.44269504f * rsqrtf((float)DIM);

    const int il0 = rg * 16 + (lane >> 2);
    const int gr  = q0 + il0;
    const int hi4 = lane >> 4;
    const int lo7 = lane & 7;
    const int cbl = (lane >> 3) & 1;
    const int rbl = (lane & 7) + ((lane >> 4) << 3);

    const uint32_t qbH = sb + OQH + (uint32_t)((rg * 16 + (lane & 15)) * 256);
    const uint32_t qbL = sb + OQL + (uint32_t)((rg * 16 + (lane & 15)) * 256);
    const uint32_t pbH = sb + OPH + (uint32_t)((rg * 16 + (lane & 15)) * 128);
    const uint32_t pbL = sb + OPL + (uint32_t)((rg * 16 + (lane & 15)) * 128);
    const uint32_t vbH = sb + OVH + (uint32_t)((lane & 15) * 256);
    const uint32_t vbL = sb + OVL + (uint32_t)((lane & 15) * 256);
    const uint32_t krow0 = (uint32_t)(((nh * 2 + 0) * 16 + rbl) * 256);
    const uint32_t krow1 = (uint32_t)(((nh * 2 + 1) * 16 + rbl) * 256);

    int lo = q0 - (w - 1);              if (lo < 0) lo = 0;
    int hi = q0 + BQ - 1 + (w - 1);     if (hi > S_LEN - 1) hi = S_LEN - 1;
    const int t0 = lo >> 6, t1 = hi >> 6;
    const int rlo = q0 + rg * 16, rhi = rlo + 15;

    const char* kvbase = g_kv + ((size_t)b * NT64) * 4 * TILEB;

    // ---- prologue group: K(t0) + V(t0) ----
    {
        const char* src = kvbase + (size_t)t0 * 4 * TILEB;
        #pragma unroll
        for (int i = 0; i < 8; i++) {
            int off = tid * 16 + i * 4096;
            cp16(sb + OKH + off, src + off);
        }
        #pragma unroll
        for (int i = 0; i < 8; i++) {
            int off = tid * 16 + i * 4096;
            cp16(sb + OVH + off, src + 2 * TILEB + off);
        }
        CP_COMMIT();
    }

    // ---- Q -> smem (hi/lo, swizzled), overlaps prologue copies ----
    {
        const float4* qg = reinterpret_cast<const float4*>(gq + ((size_t)b * S_LEN + q0) * DIM);
        #pragma unroll
        for (int i = 0; i < 8; i++) {
            int idx = tid + i * NT;
            int row = idx >> 5, c4 = idx & 31;
            int chunk = c4 >> 1, sub = (c4 & 1) << 3;
            float4 vv = qg[idx];
            uint32_t h0, l0, h1, l1;
            split2(vv.x * scale, vv.y * scale, h0, l0);
            split2(vv.z * scale, vv.w * scale, h1, l1);
            int off = row * 256 + ((chunk ^ (row & 7)) << 4) + sub;
            *reinterpret_cast<uint2*>(smc + OQH + off) = make_uint2(h0, h1);
            *reinterpret_cast<uint2*>(smc + OQL + off) = make_uint2(l0, l1);
        }
    }

    float o[8][4];
    #pragma unroll
    for (int n = 0; n < 8; n++)
        #pragma unroll
        for (int e = 0; e < 4; e++) o[n][e] = 0.f;
    float c[4][4];
    #pragma unroll
    for (int n = 0; n < 4; n++)
        #pragma unroll
        for (int e = 0; e < 4; e++) c[n][e] = 0.f;
    float rs0 = 0.f, rs1 = 0.f;

    // skip predicate helper (uniform per warp)
    auto skq_of = [&](int k0t, int np2) {
        int kb0 = k0t + nh * 32 + np2 * 16;
        return (kb0 - rhi >= w) || (rlo - (kb0 + 15) >= w);
    };

    CP_WAIT0();
    __syncthreads();               // Q + K(t0) + V(t0) visible

    // ---- QK(t0): 3 bf16 passes ----
    {
        const int k0 = t0 << 6;
        bool s0 = skq_of(k0, 0), s1 = skq_of(k0, 1);
        qk_pass(c, qbH, sb + OKH,         s0, s1, krow0, krow1, hi4, lo7, cbl);
        qk_pass(c, qbH, sb + OKH + TILEB, s0, s1, krow0, krow1, hi4, lo7, cbl);
        qk_pass(c, qbL, sb + OKH,         s0, s1, krow0, krow1, hi4, lo7, cbl);
    }
    __syncthreads();               // K(t0) consumed
    if (t0 < t1) {                 // prefetch K(t0+1)
        const char* src = kvbase + (size_t)(t0 + 1) * 4 * TILEB;
        #pragma unroll
        for (int i = 0; i < 8; i++) {
            int off = tid * 16 + i * 4096;
            cp16(sb + OKH + off, src + off);
        }
        CP_COMMIT();
    }

    for (int t = t0; t <= t1; t++) {
        const int k0 = t << 6;
        const bool doQK = (t < t1);
        const int k0n = (t + 1) << 6;
        bool sq0 = doQK ? skq_of(k0n, 0) : true;
        bool sq1 = doQK ? skq_of(k0n, 1) : true;
        bool skp[4];
        #pragma unroll
        for (int kk2 = 0; kk2 < 4; kk2++) {
            int kb0 = k0 + kk2 * 16;
            skp[kk2] = (kb0 - rhi >= w) || (rlo - (kb0 + 15) >= w);
        }

        // ---- mask + exp2 + partial rowsum (from c = S(t)) ----
        float ps0 = 0.f, ps1 = 0.f;
        #pragma unroll
        for (int j = 0; j < 4; j++) {
            int jg = k0 + nh * 32 + j * 8 + ((lane & 3) << 1);
            int d0 = gr - jg;
            float e;
            e = (d0 < w && d0 > -w)         ? ex2(c[j][0]) : 0.f; c[j][0] = e; ps0 += e;
            e = (d0 - 1 < w && d0 - 1 > -w) ? ex2(c[j][1]) : 0.f; c[j][1] = e; ps0 += e;
            e = (d0 + 8 < w && d0 + 8 > -w) ? ex2(c[j][2]) : 0.f; c[j][2] = e; ps1 += e;
            e = (d0 + 7 < w && d0 + 7 > -w) ? ex2(c[j][3]) : 0.f; c[j][3] = e; ps1 += e;
        }
        ps0 += __shfl_xor_sync(0xffffffffu, ps0, 1);
        ps0 += __shfl_xor_sync(0xffffffffu, ps0, 2);
        ps1 += __shfl_xor_sync(0xffffffffu, ps1, 1);
        ps1 += __shfl_xor_sync(0xffffffffu, ps1, 2);
        rs0 += ps0; rs1 += ps1;

        // ---- P(t) -> smem (bf16 hi/lo), then zero c for QK(t+1) ----
        #pragma unroll
        for (int j = 0; j < 4; j++) {
            uint32_t h, l;
            int off0 = il0 * 128 + (((nh * 4 + j) ^ (il0 & 7)) << 4) + ((lane & 3) << 2);
            split2(c[j][0], c[j][1], h, l);
            *reinterpret_cast<uint32_t*>(smc + OPH + off0) = h;
            *reinterpret_cast<uint32_t*>(smc + OPL + off0) = l;
            int r1 = il0 + 8;
            int off1 = r1 * 128 + (((nh * 4 + j) ^ (r1 & 7)) << 4) + ((lane & 3) << 2);
            split2(c[j][2], c[j][3], h, l);
            *reinterpret_cast<uint32_t*>(smc + OPH + off1) = h;
            *reinterpret_cast<uint32_t*>(smc + OPL + off1) = l;
        }
        #pragma unroll
        for (int n = 0; n < 4; n++)
            #pragma unroll
            for (int e = 0; e < 4; e++) c[n][e] = 0.f;

        CP_WAIT0();                // V(t) [+K(t+1)] arrived
        __syncthreads();           // P + V(t) + K(t+1) visible CTA-wide

        // ---- fused MMA phase: PV(t) passes interleaved with QK(t+1) passes ----
        if (doQK) qk_pass(c, qbH, sb + OKH,         sq0, sq1, krow0, krow1, hi4, lo7, cbl);
        pv_pass(o, pbH, vbH, skp, hi4, lo7, nh);
        if (doQK) qk_pass(c, qbH, sb + OKH + TILEB, sq0, sq1, krow0, krow1, hi4, lo7, cbl);
        pv_pass(o, pbH, vbL, skp, hi4, lo7, nh);
        if (doQK) qk_pass(c, qbL, sb + OKH,         sq0, sq1, krow0, krow1, hi4, lo7, cbl);
        pv_pass(o, pbL, vbH, skp, hi4, lo7, nh);

        __syncthreads();           // K(t+1), V(t), P(t) consumed

        if (t < t1) {              // prefetch V(t+1) [+ K(t+2)]
            const char* srcv = kvbase + (size_t)(t + 1) * 4 * TILEB;
            #pragma unroll
            for (int i = 0; i < 8; i++) {
                int off = tid * 16 + i * 4096;
                cp16(sb + OVH + off, srcv + 2 * TILEB + off);
            }
            if (t + 1 < t1) {
                const char* srck = kvbase + (size_t)(t + 2) * 4 * TILEB;
                #pragma unroll
                for (int i = 0; i < 8; i++) {
                    int off = tid * 16 + i * 4096;
                    cp16(sb + OKH + off, srck + off);
                }
            }
            CP_COMMIT();
        }
    }

    // ================= rowsum combine + normalize + store =================
    __syncthreads();
    float* rsb = reinterpret_cast<float*>(smc + ORS);
    if ((lane & 3) == 0) {
        rsb[nh * 64 + il0]     = rs0;
        rsb[nh * 64 + il0 + 8] = rs1;
    }
    __syncthreads();
    const float inv0 = 1.0f / (rsb[il0]     + rsb[64 + il0]);
    const float inv1 = 1.0f / (rsb[il0 + 8] + rsb[64 + il0 + 8]);

    float* stg = reinterpret_cast<float*>(smc + OSTG);
    const int jd = (lane & 3) << 1;
    #pragma unroll
    for (int n = 0; n < 8; n++) {
        int col = nh * 64 + n * 8 + jd;
        *reinterpret_cast<float2*>(&stg[il0 * 132 + col]) =
            make_float2(o[n][0] * inv0, o[n][1] * inv0);
        *reinterpret_cast<float2*>(&stg[(il0 + 8) * 132 + col]) =
            make_float2(o[n][2] * inv1, o[n][3] * inv1);
    }
    __syncthreads();
    float4* og = reinterpret_cast<float4*>(gout + ((size_t)b * S_LEN + q0) * DIM);
    #pragma unroll
    for (int i = 0; i < 8; i++) {
        int idx = tid + i * NT;
        int row = idx >> 5, c4 = idx & 31;
        og[idx] = *reinterpret_cast<float4*>(&stg[row * 132 + c4 * 4]);
    }
}

extern "C" void kernel_launch(void* const* d_in, const int* in_sizes, int n_in,
                              void* d_out, int out_size) {
    const float* q = (const float*)d_in[0];
    const float* k = (const float*)d_in[1];
    const float* v = (const float*)d_in[2];
    const int*   w = (const int*)d_in[3];
    const int B = in_sizes[0] / (S_LEN * DIM);
    float* out = (float*)d_out;

    conv_kv_kernel<<<dim3(NT64, B), NT>>>(k, v);

    cudaFuncSetAttribute(swa_mma_kernel, cudaFuncAttributeMaxDynamicSharedMemorySize, SMEM_BYTES);
    dim3 grid(S_LEN / BQ, B);
    swa_mma_kernel<<<grid, NT, SMEM_BYTES>>>(q, w, out);
}

// round 10
// speedup vs baseline: 1.6751x; 1.0612x over previous
#include <cuda_runtime.h>
#include <cuda_bf16.h>
#include <cstdint>
#include <math.h>

#define S_LEN 4096
#define DIM   128
#define BQ    64
#define BK    64
#define NT    256
#define NT64  (S_LEN / 64)
#define TILEB 16384

// K/V pre-converted scratch: [B][tile][Kh,Kl,Vh,Vl][16KB] = 16MB
__device__ __align__(16) char g_kv[4 * NT64 * 4 * TILEB];

// per-CTA smem byte offsets
#define OQH 0
#define OQL 16384
#define OKH 32768            // Kh(16K)+Kl(16K)
#define OVH 65536            // Vh(16K)+Vl(16K)
#define OVL 81920
#define OPH 98304
#define OPL 106496
#define SMEM_BYTES 114688
#define ORS OKH
#define OSTG (OKH + 1024)

__device__ __forceinline__ uint32_t s2u(const void* p) {
    uint32_t a;
    asm("{ .reg .u64 t; cvta.to.shared.u64 t, %1; cvt.u32.u64 %0, t; }" : "=r"(a) : "l"(p));
    return a;
}
__device__ __forceinline__ void ldm4(uint32_t a, uint32_t* r) {
    asm volatile("ldmatrix.sync.aligned.m8n8.x4.shared.b16 {%0,%1,%2,%3}, [%4];"
                 : "=r"(r[0]), "=r"(r[1]), "=r"(r[2]), "=r"(r[3]) : "r"(a));
}
__device__ __forceinline__ void ldm4t(uint32_t a, uint32_t* r) {
    asm volatile("ldmatrix.sync.aligned.m8n8.x4.trans.shared.b16 {%0,%1,%2,%3}, [%4];"
                 : "=r"(r[0]), "=r"(r[1]), "=r"(r[2]), "=r"(r[3]) : "r"(a));
}
__device__ __forceinline__ void mma_bf16(float* c, const uint32_t* a, uint32_t b0, uint32_t b1) {
    asm volatile("mma.sync.aligned.m16n8k16.row.col.f32.bf16.bf16.f32 "
                 "{%0,%1,%2,%3}, {%4,%5,%6,%7}, {%8,%9}, {%0,%1,%2,%3};"
                 : "+f"(c[0]), "+f"(c[1]), "+f"(c[2]), "+f"(c[3])
                 : "r"(a[0]), "r"(a[1]), "r"(a[2]), "r"(a[3]), "r"(b0), "r"(b1));
}
__device__ __forceinline__ void split2(float x, float y, uint32_t& hi, uint32_t& lo) {
    __nv_bfloat162 h = __floats2bfloat162_rn(x, y);
    float rx = x - __bfloat162float(h.x);
    float ry = y - __bfloat162float(h.y);
    __nv_bfloat162 l = __floats2bfloat162_rn(rx, ry);
    hi = *reinterpret_cast<uint32_t*>(&h);
    lo = *reinterpret_cast<uint32_t*>(&l);
}
__device__ __forceinline__ float ex2(float x) {
    float r;
    asm("ex2.approx.f32 %0, %1;" : "=f"(r) : "f"(x));
    return r;
}
__device__ __forceinline__ void cp16(uint32_t dst, const char* src) {
    asm volatile("cp.async.cg.shared.global [%0], [%1], 16;" :: "r"(dst), "l"(src));
}
#define CP_COMMIT() asm volatile("cp.async.commit_group;")
#define CP_WAIT0()  asm volatile("cp.async.wait_group 0;")

// ---- fused 3-term QK: each fragment loaded ONCE; terms Ah*Kh, Al*Kh, Ah*Kl ----
__device__ __forceinline__ void qk_fused(float (*c)[4], uint32_t qbH, uint32_t qbL,
                                         uint32_t kbH, uint32_t kbL,
                                         bool sk0, bool sk1, uint32_t krow0, uint32_t krow1,
                                         int hi4, int lo7, int cbl, int kk0, int kk1) {
    #pragma unroll
    for (int kk = kk0; kk < kk1; kk++) {
        uint32_t Ah[4], Al[4];
        uint32_t qcol = (uint32_t)(((2 * kk + hi4) ^ lo7) << 4);
        ldm4(qbH + qcol, Ah);
        ldm4(qbL + qcol, Al);
        uint32_t kcol = (uint32_t)(((2 * kk + cbl) ^ lo7) << 4);
        uint32_t b0[4], b1[4];
        if (!sk0) ldm4(kbH + krow0 + kcol, b0);
        if (!sk1) ldm4(kbH + krow1 + kcol, b1);
        if (!sk0) { mma_bf16(c[0], Ah, b0[0], b0[1]); mma_bf16(c[1], Ah, b0[2], b0[3]); }
        if (!sk1) { mma_bf16(c[2], Ah, b1[0], b1[1]); mma_bf16(c[3], Ah, b1[2], b1[3]); }
        if (!sk0) { mma_bf16(c[0], Al, b0[0], b0[1]); mma_bf16(c[1], Al, b0[2], b0[3]); }
        if (!sk1) { mma_bf16(c[2], Al, b1[0], b1[1]); mma_bf16(c[3], Al, b1[2], b1[3]); }
        if (!sk0) {
            ldm4(kbL + krow0 + kcol, b0);
            mma_bf16(c[0], Ah, b0[0], b0[1]); mma_bf16(c[1], Ah, b0[2], b0[3]);
        }
        if (!sk1) {
            ldm4(kbL + krow1 + kcol, b1);
            mma_bf16(c[2], Ah, b1[0], b1[1]); mma_bf16(c[3], Ah, b1[2], b1[3]);
        }
    }
}

// ---- fused 3-term PV: terms Ph*Vh, Pl*Vh, Ph*Vl; each fragment loaded ONCE ----
__device__ __forceinline__ void pv_fused(float (*o)[4], uint32_t pbH, uint32_t pbL,
                                         uint32_t vbH, uint32_t vbL,
                                         const bool* skp, int hi4, int lo7, int nh) {
    #pragma unroll
    for (int kk2 = 0; kk2 < 4; kk2++) {
        if (!skp[kk2]) {
            uint32_t pcol = (uint32_t)(((2 * kk2 + hi4) ^ lo7) << 4);
            uint32_t ph[4], pl[4];
            ldm4(pbH + pcol, ph);
            ldm4(pbL + pcol, pl);
            uint32_t vrow = (uint32_t)(kk2 * 16 * 256);
            #pragma unroll
            for (int vp2 = 0; vp2 < 4; vp2++) {
                uint32_t vcol = vrow + (uint32_t)(((nh * 8 + 2 * vp2 + hi4) ^ lo7) << 4);
                uint32_t bh[4];
                ldm4t(vbH + vcol, bh);
                mma_bf16(o[vp2 * 2],     ph, bh[0], bh[1]);
                mma_bf16(o[vp2 * 2 + 1], ph, bh[2], bh[3]);
                mma_bf16(o[vp2 * 2],     pl, bh[0], bh[1]);
                mma_bf16(o[vp2 * 2 + 1], pl, bh[2], bh[3]);
                uint32_t bl[4];
                ldm4t(vbL + vcol, bl);
                mma_bf16(o[vp2 * 2],     ph, bl[0], bl[1]);
                mma_bf16(o[vp2 * 2 + 1], ph, bl[2], bl[3]);
            }
        }
    }
}

// ================= pre-convert: K,V fp32 -> bf16 hi/lo swizzled tile images =================
__global__ __launch_bounds__(NT, 4)
void conv_kv_kernel(const float* __restrict__ gk, const float* __restrict__ gv) {
    const int t = blockIdx.x, b = blockIdx.y, tid = threadIdx.x;
    char* dst = g_kv + ((size_t)(b * NT64 + t)) * 4 * TILEB;
    const float4* kg = reinterpret_cast<const float4*>(gk + ((size_t)b * S_LEN + t * 64) * DIM);
    const float4* vg = reinterpret_cast<const float4*>(gv + ((size_t)b * S_LEN + t * 64) * DIM);
    #pragma unroll
    for (int i = 0; i < 8; i++) {
        int idx = tid + i * NT;
        int row = idx >> 5, c4 = idx & 31;
        int chunk = c4 >> 1, sub = (c4 & 1) << 3;
        int off = row * 256 + ((chunk ^ (row & 7)) << 4) + sub;
        float4 kv = kg[idx];
        uint32_t h0, l0, h1, l1;
        split2(kv.x, kv.y, h0, l0);
        split2(kv.z, kv.w, h1, l1);
        *reinterpret_cast<uint2*>(dst + off)             = make_uint2(h0, h1);
        *reinterpret_cast<uint2*>(dst + TILEB + off)     = make_uint2(l0, l1);
        float4 vv = vg[idx];
        split2(vv.x, vv.y, h0, l0);
        split2(vv.z, vv.w, h1, l1);
        *reinterpret_cast<uint2*>(dst + 2 * TILEB + off) = make_uint2(h0, h1);
        *reinterpret_cast<uint2*>(dst + 3 * TILEB + off) = make_uint2(l0, l1);
    }
}

// ================= main attention kernel (pipelined, fused 3-term MMA loops) =================
__global__ __launch_bounds__(NT, 2)
void swa_mma_kernel(const float* __restrict__ gq, const int* __restrict__ wptr,
                    float* __restrict__ gout)
{
    extern __shared__ char smc[];
    const uint32_t sb = s2u(smc);
    const int tid = threadIdx.x, lane = tid & 31, wr = tid >> 5;
    const int rg = wr & 3;
    const int nh = wr >> 2;
    const int q0 = blockIdx.x * BQ, b = blockIdx.y;
    const int w = wptr[0];
    const float scale = 1.44269504f * rsqrtf((float)DIM);

    const int il0 = rg * 16 + (lane >> 2);
    const int gr  = q0 + il0;
    const int hi4 = lane >> 4;
    const int lo7 = lane & 7;
    const int cbl = (lane >> 3) & 1;
    const int rbl = (lane & 7) + ((lane >> 4) << 3);

    const uint32_t qbH = sb + OQH + (uint32_t)((rg * 16 + (lane & 15)) * 256);
    const uint32_t qbL = sb + OQL + (uint32_t)((rg * 16 + (lane & 15)) * 256);
    const uint32_t pbH = sb + OPH + (uint32_t)((rg * 16 + (lane & 15)) * 128);
    const uint32_t pbL = sb + OPL + (uint32_t)((rg * 16 + (lane & 15)) * 128);
    const uint32_t vbH = sb + OVH + (uint32_t)((lane & 15) * 256);
    const uint32_t vbL = sb + OVL + (uint32_t)((lane & 15) * 256);
    const uint32_t krow0 = (uint32_t)(((nh * 2 + 0) * 16 + rbl) * 256);
    const uint32_t krow1 = (uint32_t)(((nh * 2 + 1) * 16 + rbl) * 256);

    int lo = q0 - (w - 1);              if (lo < 0) lo = 0;
    int hi = q0 + BQ - 1 + (w - 1);     if (hi > S_LEN - 1) hi = S_LEN - 1;
    const int t0 = lo >> 6, t1 = hi >> 6;
    const int rlo = q0 + rg * 16, rhi = rlo + 15;

    const char* kvbase = g_kv + ((size_t)b * NT64) * 4 * TILEB;

    // ---- prologue group: K(t0) + V(t0) ----
    {
        const char* src = kvbase + (size_t)t0 * 4 * TILEB;
        #pragma unroll
        for (int i = 0; i < 8; i++) {
            int off = tid * 16 + i * 4096;
            cp16(sb + OKH + off, src + off);
        }
        #pragma unroll
        for (int i = 0; i < 8; i++) {
            int off = tid * 16 + i * 4096;
            cp16(sb + OVH + off, src + 2 * TILEB + off);
        }
        CP_COMMIT();
    }

    // ---- Q -> smem (hi/lo, swizzled), overlaps prologue copies ----
    {
        const float4* qg = reinterpret_cast<const float4*>(gq + ((size_t)b * S_LEN + q0) * DIM);
        #pragma unroll
        for (int i = 0; i < 8; i++) {
            int idx = tid + i * NT;
            int row = idx >> 5, c4 = idx & 31;
            int chunk = c4 >> 1, sub = (c4 & 1) << 3;
            float4 vv = qg[idx];
            uint32_t h0, l0, h1, l1;
            split2(vv.x * scale, vv.y * scale, h0, l0);
            split2(vv.z * scale, vv.w * scale, h1, l1);
            int off = row * 256 + ((chunk ^ (row & 7)) << 4) + sub;
            *reinterpret_cast<uint2*>(smc + OQH + off) = make_uint2(h0, h1);
            *reinterpret_cast<uint2*>(smc + OQL + off) = make_uint2(l0, l1);
        }
    }

    float o[8][4];
    #pragma unroll
    for (int n = 0; n < 8; n++)
        #pragma unroll
        for (int e = 0; e < 4; e++) o[n][e] = 0.f;
    float c[4][4];
    #pragma unroll
    for (int n = 0; n < 4; n++)
        #pragma unroll
        for (int e = 0; e < 4; e++) c[n][e] = 0.f;
    float rs0 = 0.f, rs1 = 0.f;

    auto skq_of = [&](int k0t, int np2) {
        int kb0 = k0t + nh * 32 + np2 * 16;
        return (kb0 - rhi >= w) || (rlo - (kb0 + 15) >= w);
    };

    CP_WAIT0();
    __syncthreads();               // Q + K(t0) + V(t0) visible

    // ---- QK(t0) fused ----
    {
        const int k0 = t0 << 6;
        bool s0 = skq_of(k0, 0), s1 = skq_of(k0, 1);
        qk_fused(c, qbH, qbL, sb + OKH, sb + OKH + TILEB, s0, s1,
                 krow0, krow1, hi4, lo7, cbl, 0, 8);
    }
    __syncthreads();               // K(t0) consumed
    if (t0 < t1) {                 // prefetch K(t0+1)
        const char* src = kvbase + (size_t)(t0 + 1) * 4 * TILEB;
        #pragma unroll
        for (int i = 0; i < 8; i++) {
            int off = tid * 16 + i * 4096;
            cp16(sb + OKH + off, src + off);
        }
        CP_COMMIT();
    }

    for (int t = t0; t <= t1; t++) {
        const int k0 = t << 6;
        const bool doQK = (t < t1);
        const int k0n = (t + 1) << 6;
        bool sq0 = doQK ? skq_of(k0n, 0) : true;
        bool sq1 = doQK ? skq_of(k0n, 1) : true;
        bool skp[4];
        #pragma unroll
        for (int kk2 = 0; kk2 < 4; kk2++) {
            int kb0 = k0 + kk2 * 16;
            skp[kk2] = (kb0 - rhi >= w) || (rlo - (kb0 + 15) >= w);
        }

        // ---- mask + exp2 + partial rowsum ----
        float ps0 = 0.f, ps1 = 0.f;
        #pragma unroll
        for (int j = 0; j < 4; j++) {
            int jg = k0 + nh * 32 + j * 8 + ((lane & 3) << 1);
            int d0 = gr - jg;
            float e;
            e = (d0 < w && d0 > -w)         ? ex2(c[j][0]) : 0.f; c[j][0] = e; ps0 += e;
            e = (d0 - 1 < w && d0 - 1 > -w) ? ex2(c[j][1]) : 0.f; c[j][1] = e; ps0 += e;
            e = (d0 + 8 < w && d0 + 8 > -w) ? ex2(c[j][2]) : 0.f; c[j][2] = e; ps1 += e;
            e = (d0 + 7 < w && d0 + 7 > -w) ? ex2(c[j][3]) : 0.f; c[j][3] = e; ps1 += e;
        }
        ps0 += __shfl_xor_sync(0xffffffffu, ps0, 1);
        ps0 += __shfl_xor_sync(0xffffffffu, ps0, 2);
        ps1 += __shfl_xor_sync(0xffffffffu, ps1, 1);
        ps1 += __shfl_xor_sync(0xffffffffu, ps1, 2);
        rs0 += ps0; rs1 += ps1;

        // ---- P(t) -> smem (bf16 hi/lo), then zero c ----
        #pragma unroll
        for (int j = 0; j < 4; j++) {
            uint32_t h, l;
            int off0 = il0 * 128 + (((nh * 4 + j) ^ (il0 & 7)) << 4) + ((lane & 3) << 2);
            split2(c[j][0], c[j][1], h, l);
            *reinterpret_cast<uint32_t*>(smc + OPH + off0) = h;
            *reinterpret_cast<uint32_t*>(smc + OPL + off0) = l;
            int r1 = il0 + 8;
            int off1 = r1 * 128 + (((nh * 4 + j) ^ (r1 & 7)) << 4) + ((lane & 3) << 2);
            split2(c[j][2], c[j][3], h, l);
            *reinterpret_cast<uint32_t*>(smc + OPH + off1) = h;
            *reinterpret_cast<uint32_t*>(smc + OPL + off1) = l;
        }
        #pragma unroll
        for (int n = 0; n < 4; n++)
            #pragma unroll
            for (int e = 0; e < 4; e++) c[n][e] = 0.f;

        CP_WAIT0();                // V(t) [+K(t+1)] arrived
        __syncthreads();           // P + V(t) + K(t+1) visible CTA-wide

        // ---- fused MMA phase: QK(t+1) halves around PV(t) ----
        if (doQK) qk_fused(c, qbH, qbL, sb + OKH, sb + OKH + TILEB, sq0, sq1,
                           krow0, krow1, hi4, lo7, cbl, 0, 4);
        pv_fused(o, pbH, pbL, vbH, vbL, skp, hi4, lo7, nh);
        if (doQK) qk_fused(c, qbH, qbL, sb + OKH, sb + OKH + TILEB, sq0, sq1,
                           krow0, krow1, hi4, lo7, cbl, 4, 8);

        __syncthreads();           // K(t+1), V(t), P(t) consumed

        if (t < t1) {              // prefetch V(t+1) [+ K(t+2)]
            const char* srcv = kvbase + (size_t)(t + 1) * 4 * TILEB;
            #pragma unroll
            for (int i = 0; i < 8; i++) {
                int off = tid * 16 + i * 4096;
                cp16(sb + OVH + off, srcv + 2 * TILEB + off);
            }
            if (t + 1 < t1) {
                const char* srck = kvbase + (size_t)(t + 2) * 4 * TILEB;
                #pragma unroll
                for (int i = 0; i < 8; i++) {
                    int off = tid * 16 + i * 4096;
                    cp16(sb + OKH + off, srck + off);
                }
            }
            CP_COMMIT();
        }
    }

    // ================= rowsum combine + normalize + store =================
    __syncthreads();
    float* rsb = reinterpret_cast<float*>(smc + ORS);
    if ((lane & 3) == 0) {
        rsb[nh * 64 + il0]     = rs0;
        rsb[nh * 64 + il0 + 8] = rs1;
    }
    __syncthreads();
    const float inv0 = 1.0f / (rsb[il0]     + rsb[64 + il0]);
    const float inv1 = 1.0f / (rsb[il0 + 8] + rsb[64 + il0 + 8]);

    float* stg = reinterpret_cast<float*>(smc + OSTG);
    const int jd = (lane & 3) << 1;
    #pragma unroll
    for (int n = 0; n < 8; n++) {
        int col = nh * 64 + n * 8 + jd;
        *reinterpret_cast<float2*>(&stg[il0 * 132 + col]) =
            make_float2(o[n][0] * inv0, o[n][1] * inv0);
        *reinterpret_cast<float2*>(&stg[(il0 + 8) * 132 + col]) =
            make_float2(o[n][2] * inv1, o[n][3] * inv1);
    }
    __syncthreads();
    float4* og = reinterpret_cast<float4*>(gout + ((size_t)b * S_LEN + q0) * DIM);
    #pragma unroll
    for (int i = 0; i < 8; i++) {
        int idx = tid + i * NT;
        int row = idx >> 5, c4 = idx & 31;
        og[idx] = *reinterpret_cast<float4*>(&stg[row * 132 + c4 * 4]);
    }
}

extern "C" void kernel_launch(void* const* d_in, const int* in_sizes, int n_in,
                              void* d_out, int out_size) {
    const float* q = (const float*)d_in[0];
    const float* k = (const float*)d_in[1];
    const float* v = (const float*)d_in[2];
    const int*   w = (const int*)d_in[3];
    const int B = in_sizes[0] / (S_LEN * DIM);
    float* out = (float*)d_out;

    conv_kv_kernel<<<dim3(NT64, B), NT>>>(k, v);

    cudaFuncSetAttribute(swa_mma_kernel, cudaFuncAttributeMaxDynamicSharedMemorySize, SMEM_BYTES);
    dim3 grid(S_LEN / BQ, B);
    swa_mma_kernel<<<grid, NT, SMEM_BYTES>>>(q, w, out);
}

// round 11
// speedup vs baseline: 2.1741x; 1.2979x over previous
#include <cuda_runtime.h>
#include <cuda_fp16.h>
#include <cstdint>
#include <math.h>

#define S_LEN 4096
#define DIM   128
#define BQ    64
#define BK    64
#define NT    256
#define NT64  (S_LEN / 64)
#define TILEB 16384

// K/V pre-converted scratch: [B][tile][Kh,Vh][16KB] = 8MB (fp16 single)
__device__ __align__(16) char g_kv[4 * NT64 * 2 * TILEB];

// per-CTA smem byte offsets
#define OQH 0
#define OQL 16384
#define OK  32768
#define OV  49152
#define OPH 65536
#define OPL 73728
#define SMEM_BYTES 81920
#define ORS OK
#define OSTG (OK + 1024)

__device__ __forceinline__ uint32_t s2u(const void* p) {
    uint32_t a;
    asm("{ .reg .u64 t; cvta.to.shared.u64 t, %1; cvt.u32.u64 %0, t; }" : "=r"(a) : "l"(p));
    return a;
}
__device__ __forceinline__ void ldm4(uint32_t a, uint32_t* r) {
    asm volatile("ldmatrix.sync.aligned.m8n8.x4.shared.b16 {%0,%1,%2,%3}, [%4];"
                 : "=r"(r[0]), "=r"(r[1]), "=r"(r[2]), "=r"(r[3]) : "r"(a));
}
__device__ __forceinline__ void ldm4t(uint32_t a, uint32_t* r) {
    asm volatile("ldmatrix.sync.aligned.m8n8.x4.trans.shared.b16 {%0,%1,%2,%3}, [%4];"
                 : "=r"(r[0]), "=r"(r[1]), "=r"(r[2]), "=r"(r[3]) : "r"(a));
}
__device__ __forceinline__ void mma_f16(float* c, const uint32_t* a, uint32_t b0, uint32_t b1) {
    asm volatile("mma.sync.aligned.m16n8k16.row.col.f32.f16.f16.f32 "
                 "{%0,%1,%2,%3}, {%4,%5,%6,%7}, {%8,%9}, {%0,%1,%2,%3};"
                 : "+f"(c[0]), "+f"(c[1]), "+f"(c[2]), "+f"(c[3])
                 : "r"(a[0]), "r"(a[1]), "r"(a[2]), "r"(a[3]), "r"(b0), "r"(b1));
}
__device__ __forceinline__ uint32_t h2u(__half2 h) { return *reinterpret_cast<uint32_t*>(&h); }
__device__ __forceinline__ void split2h(float x, float y, uint32_t& hi, uint32_t& lo) {
    __half2 h = __floats2half2_rn(x, y);
    float rx = x - __half2float(__low2half(h));
    float ry = y - __half2float(__high2half(h));
    __half2 l = __floats2half2_rn(rx, ry);
    hi = h2u(h);
    lo = h2u(l);
}
__device__ __forceinline__ float ex2(float x) {
    float r;
    asm("ex2.approx.f32 %0, %1;" : "=f"(r) : "f"(x));
    return r;
}
__device__ __forceinline__ void cp16(uint32_t dst, const char* src) {
    asm volatile("cp.async.cg.shared.global [%0], [%1], 16;" :: "r"(dst), "l"(src));
}
#define CP_COMMIT() asm volatile("cp.async.commit_group;")
#define CP_WAIT0()  asm volatile("cp.async.wait_group 0;")

// ---- 2-term QK: terms qh*Kh + ql*Kh; each fragment loaded once ----
__device__ __forceinline__ void qk_fused(float (*c)[4], uint32_t qbH, uint32_t qbL,
                                         uint32_t kb,
                                         bool sk0, bool sk1, uint32_t krow0, uint32_t krow1,
                                         int hi4, int lo7, int cbl, int kk0, int kk1) {
    #pragma unroll
    for (int kk = kk0; kk < kk1; kk++) {
        uint32_t Ah[4], Al[4];
        uint32_t qcol = (uint32_t)(((2 * kk + hi4) ^ lo7) << 4);
        ldm4(qbH + qcol, Ah);
        ldm4(qbL + qcol, Al);
        uint32_t kcol = (uint32_t)(((2 * kk + cbl) ^ lo7) << 4);
        if (!sk0) {
            uint32_t b0[4];
            ldm4(kb + krow0 + kcol, b0);
            mma_f16(c[0], Ah, b0[0], b0[1]); mma_f16(c[1], Ah, b0[2], b0[3]);
            mma_f16(c[0], Al, b0[0], b0[1]); mma_f16(c[1], Al, b0[2], b0[3]);
        }
        if (!sk1) {
            uint32_t b1[4];
            ldm4(kb + krow1 + kcol, b1);
            mma_f16(c[2], Ah, b1[0], b1[1]); mma_f16(c[3], Ah, b1[2], b1[3]);
            mma_f16(c[2], Al, b1[0], b1[1]); mma_f16(c[3], Al, b1[2], b1[3]);
        }
    }
}

// ---- 2-term PV: terms Ph*Vh + Pl*Vh; each fragment loaded once ----
__device__ __forceinline__ void pv_fused(float (*o)[4], uint32_t pbH, uint32_t pbL,
                                         uint32_t vb, const bool* skp,
                                         int hi4, int lo7, int nh) {
    #pragma unroll
    for (int kk2 = 0; kk2 < 4; kk2++) {
        if (!skp[kk2]) {
            uint32_t pcol = (uint32_t)(((2 * kk2 + hi4) ^ lo7) << 4);
            uint32_t ph[4], pl[4];
            ldm4(pbH + pcol, ph);
            ldm4(pbL + pcol, pl);
            uint32_t vrow = (uint32_t)(kk2 * 16 * 256);
            #pragma unroll
            for (int vp2 = 0; vp2 < 4; vp2++) {
                uint32_t vcol = vrow + (uint32_t)(((nh * 8 + 2 * vp2 + hi4) ^ lo7) << 4);
                uint32_t bh[4];
                ldm4t(vb + vcol, bh);
                mma_f16(o[vp2 * 2],     ph, bh[0], bh[1]);
                mma_f16(o[vp2 * 2 + 1], ph, bh[2], bh[3]);
                mma_f16(o[vp2 * 2],     pl, bh[0], bh[1]);
                mma_f16(o[vp2 * 2 + 1], pl, bh[2], bh[3]);
            }
        }
    }
}

// ================= pre-convert: K,V fp32 -> fp16 swizzled tile images =================
__global__ __launch_bounds__(NT, 4)
void conv_kv_kernel(const float* __restrict__ gk, const float* __restrict__ gv) {
    const int t = blockIdx.x, b = blockIdx.y, tid = threadIdx.x;
    char* dst = g_kv + ((size_t)(b * NT64 + t)) * 2 * TILEB;
    const float4* kg = reinterpret_cast<const float4*>(gk + ((size_t)b * S_LEN + t * 64) * DIM);
    const float4* vg = reinterpret_cast<const float4*>(gv + ((size_t)b * S_LEN + t * 64) * DIM);
    #pragma unroll
    for (int i = 0; i < 8; i++) {
        int idx = tid + i * NT;
        int row = idx >> 5, c4 = idx & 31;
        int chunk = c4 >> 1, sub = (c4 & 1) << 3;
        int off = row * 256 + ((chunk ^ (row & 7)) << 4) + sub;
        float4 kv = kg[idx];
        *reinterpret_cast<uint2*>(dst + off) =
            make_uint2(h2u(__floats2half2_rn(kv.x, kv.y)), h2u(__floats2half2_rn(kv.z, kv.w)));
        float4 vv = vg[idx];
        *reinterpret_cast<uint2*>(dst + TILEB + off) =
            make_uint2(h2u(__floats2half2_rn(vv.x, vv.y)), h2u(__floats2half2_rn(vv.z, vv.w)));
    }
}

// ================= main attention kernel (pipelined, 2-term fp16 MMA) =================
__global__ __launch_bounds__(NT, 2)
void swa_mma_kernel(const float* __restrict__ gq, const int* __restrict__ wptr,
                    float* __restrict__ gout)
{
    extern __shared__ char smc[];
    const uint32_t sb = s2u(smc);
    const int tid = threadIdx.x, lane = tid & 31, wr = tid >> 5;
    const int rg = wr & 3;
    const int nh = wr >> 2;
    const int q0 = blockIdx.x * BQ, b = blockIdx.y;
    const int w = wptr[0];
    const float scale = 1.44269504f * rsqrtf((float)DIM);

    const int il0 = rg * 16 + (lane >> 2);
    const int gr  = q0 + il0;
    const int hi4 = lane >> 4;
    const int lo7 = lane & 7;
    const int cbl = (lane >> 3) & 1;
    const int rbl = (lane & 7) + ((lane >> 4) << 3);

    const uint32_t qbH = sb + OQH + (uint32_t)((rg * 16 + (lane & 15)) * 256);
    const uint32_t qbL = sb + OQL + (uint32_t)((rg * 16 + (lane & 15)) * 256);
    const uint32_t pbH = sb + OPH + (uint32_t)((rg * 16 + (lane & 15)) * 128);
    const uint32_t pbL = sb + OPL + (uint32_t)((rg * 16 + (lane & 15)) * 128);
    const uint32_t vb  = sb + OV  + (uint32_t)((lane & 15) * 256);
    const uint32_t krow0 = (uint32_t)(((nh * 2 + 0) * 16 + rbl) * 256);
    const uint32_t krow1 = (uint32_t)(((nh * 2 + 1) * 16 + rbl) * 256);

    int lo = q0 - (w - 1);              if (lo < 0) lo = 0;
    int hi = q0 + BQ - 1 + (w - 1);     if (hi > S_LEN - 1) hi = S_LEN - 1;
    const int t0 = lo >> 6, t1 = hi >> 6;
    const int rlo = q0 + rg * 16, rhi = rlo + 15;

    const char* kvbase = g_kv + ((size_t)b * NT64) * 2 * TILEB;

    // ---- prologue group: K(t0) + V(t0) ----
    {
        const char* src = kvbase + (size_t)t0 * 2 * TILEB;
        #pragma unroll
        for (int i = 0; i < 4; i++) {
            int off = tid * 16 + i * 4096;
            cp16(sb + OK + off, src + off);
        }
        #pragma unroll
        for (int i = 0; i < 4; i++) {
            int off = tid * 16 + i * 4096;
            cp16(sb + OV + off, src + TILEB + off);
        }
        CP_COMMIT();
    }

    // ---- Q -> smem (fp16 hi/lo, swizzled), overlaps prologue copies ----
    {
        const float4* qg = reinterpret_cast<const float4*>(gq + ((size_t)b * S_LEN + q0) * DIM);
        #pragma unroll
        for (int i = 0; i < 8; i++) {
            int idx = tid + i * NT;
            int row = idx >> 5, c4 = idx & 31;
            int chunk = c4 >> 1, sub = (c4 & 1) << 3;
            float4 vv = qg[idx];
            uint32_t h0, l0, h1, l1;
            split2h(vv.x * scale, vv.y * scale, h0, l0);
            split2h(vv.z * scale, vv.w * scale, h1, l1);
            int off = row * 256 + ((chunk ^ (row & 7)) << 4) + sub;
            *reinterpret_cast<uint2*>(smc + OQH + off) = make_uint2(h0, h1);
            *reinterpret_cast<uint2*>(smc + OQL + off) = make_uint2(l0, l1);
        }
    }

    float o[8][4];
    #pragma unroll
    for (int n = 0; n < 8; n++)
        #pragma unroll
        for (int e = 0; e < 4; e++) o[n][e] = 0.f;
    float c[4][4];
    #pragma unroll
    for (int n = 0; n < 4; n++)
        #pragma unroll
        for (int e = 0; e < 4; e++) c[n][e] = 0.f;
    float rs0 = 0.f, rs1 = 0.f;

    auto skq_of = [&](int k0t, int np2) {
        int kb0 = k0t + nh * 32 + np2 * 16;
        return (kb0 - rhi >= w) || (rlo - (kb0 + 15) >= w);
    };

    CP_WAIT0();
    __syncthreads();               // Q + K(t0) + V(t0) visible

    // ---- QK(t0) ----
    {
        const int k0 = t0 << 6;
        bool s0 = skq_of(k0, 0), s1 = skq_of(k0, 1);
        qk_fused(c, qbH, qbL, sb + OK, s0, s1, krow0, krow1, hi4, lo7, cbl, 0, 8);
    }
    __syncthreads();               // K(t0) consumed
    if (t0 < t1) {                 // prefetch K(t0+1)
        const char* src = kvbase + (size_t)(t0 + 1) * 2 * TILEB;
        #pragma unroll
        for (int i = 0; i < 4; i++) {
            int off = tid * 16 + i * 4096;
            cp16(sb + OK + off, src + off);
        }
        CP_COMMIT();
    }

    for (int t = t0; t <= t1; t++) {
        const int k0 = t << 6;
        const bool doQK = (t < t1);
        const int k0n = (t + 1) << 6;
        bool sq0 = doQK ? skq_of(k0n, 0) : true;
        bool sq1 = doQK ? skq_of(k0n, 1) : true;
        bool skp[4];
        #pragma unroll
        for (int kk2 = 0; kk2 < 4; kk2++) {
            int kb0 = k0 + kk2 * 16;
            skp[kk2] = (kb0 - rhi >= w) || (rlo - (kb0 + 15) >= w);
        }

        // ---- mask + exp2 + partial rowsum ----
        float ps0 = 0.f, ps1 = 0.f;
        #pragma unroll
        for (int j = 0; j < 4; j++) {
            int jg = k0 + nh * 32 + j * 8 + ((lane & 3) << 1);
            int d0 = gr - jg;
            float e;
            e = (d0 < w && d0 > -w)         ? ex2(c[j][0]) : 0.f; c[j][0] = e; ps0 += e;
            e = (d0 - 1 < w && d0 - 1 > -w) ? ex2(c[j][1]) : 0.f; c[j][1] = e; ps0 += e;
            e = (d0 + 8 < w && d0 + 8 > -w) ? ex2(c[j][2]) : 0.f; c[j][2] = e; ps1 += e;
            e = (d0 + 7 < w && d0 + 7 > -w) ? ex2(c[j][3]) : 0.f; c[j][3] = e; ps1 += e;
        }
        ps0 += __shfl_xor_sync(0xffffffffu, ps0, 1);
        ps0 += __shfl_xor_sync(0xffffffffu, ps0, 2);
        ps1 += __shfl_xor_sync(0xffffffffu, ps1, 1);
        ps1 += __shfl_xor_sync(0xffffffffu, ps1, 2);
        rs0 += ps0; rs1 += ps1;

        // ---- P(t) -> smem (fp16 hi/lo), then zero c ----
        #pragma unroll
        for (int j = 0; j < 4; j++) {
            uint32_t h, l;
            int off0 = il0 * 128 + (((nh * 4 + j) ^ (il0 & 7)) << 4) + ((lane & 3) << 2);
            split2h(c[j][0], c[j][1], h, l);
            *reinterpret_cast<uint32_t*>(smc + OPH + off0) = h;
            *reinterpret_cast<uint32_t*>(smc + OPL + off0) = l;
            int r1 = il0 + 8;
            int off1 = r1 * 128 + (((nh * 4 + j) ^ (r1 & 7)) << 4) + ((lane & 3) << 2);
            split2h(c[j][2], c[j][3], h, l);
            *reinterpret_cast<uint32_t*>(smc + OPH + off1) = h;
            *reinterpret_cast<uint32_t*>(smc + OPL + off1) = l;
        }
        #pragma unroll
        for (int n = 0; n < 4; n++)
            #pragma unroll
            for (int e = 0; e < 4; e++) c[n][e] = 0.f;

        CP_WAIT0();                // V(t) [+K(t+1)] arrived
        __syncthreads();           // P + V(t) + K(t+1) visible CTA-wide

        // ---- fused MMA phase: QK(t+1) halves around PV(t) ----
        if (doQK) qk_fused(c, qbH, qbL, sb + OK, sq0, sq1, krow0, krow1, hi4, lo7, cbl, 0, 4);
        pv_fused(o, pbH, pbL, vb, skp, hi4, lo7, nh);
        if (doQK) qk_fused(c, qbH, qbL, sb + OK, sq0, sq1, krow0, krow1, hi4, lo7, cbl, 4, 8);

        __syncthreads();           // K(t+1), V(t), P(t) consumed

        if (t < t1) {              // prefetch V(t+1) [+ K(t+2)]
            const char* srcv = kvbase + (size_t)(t + 1) * 2 * TILEB;
            #pragma unroll
            for (int i = 0; i < 4; i++) {
                int off = tid * 16 + i * 4096;
                cp16(sb + OV + off, srcv + TILEB + off);
            }
            if (t + 1 < t1) {
                const char* srck = kvbase + (size_t)(t + 2) * 2 * TILEB;
                #pragma unroll
                for (int i = 0; i < 4; i++) {
                    int off = tid * 16 + i * 4096;
                    cp16(sb + OK + off, srck + off);
                }
            }
            CP_COMMIT();
        }
    }

    // ================= rowsum combine + normalize + store =================
    __syncthreads();
    float* rsb = reinterpret_cast<float*>(smc + ORS);
    if ((lane & 3) == 0) {
        rsb[nh * 64 + il0]     = rs0;
        rsb[nh * 64 + il0 + 8] = rs1;
    }
    __syncthreads();
    const float inv0 = 1.0f / (rsb[il0]     + rsb[64 + il0]);
    const float inv1 = 1.0f / (rsb[il0 + 8] + rsb[64 + il0 + 8]);

    float* stg = reinterpret_cast<float*>(smc + OSTG);
    const int jd = (lane & 3) << 1;
    #pragma unroll
    for (int n = 0; n < 8; n++) {
        int col = nh * 64 + n * 8 + jd;
        *reinterpret_cast<float2*>(&stg[il0 * 132 + col]) =
            make_float2(o[n][0] * inv0, o[n][1] * inv0);
        *reinterpret_cast<float2*>(&stg[(il0 + 8) * 132 + col]) =
            make_float2(o[n][2] * inv1, o[n][3] * inv1);
    }
    __syncthreads();
    float4* og = reinterpret_cast<float4*>(gout + ((size_t)b * S_LEN + q0) * DIM);
    #pragma unroll
    for (int i = 0; i < 8; i++) {
        int idx = tid + i * NT;
        int row = idx >> 5, c4 = idx & 31;
        og[idx] = *reinterpret_cast<float4*>(&stg[row * 132 + c4 * 4]);
    }
}

extern "C" void kernel_launch(void* const* d_in, const int* in_sizes, int n_in,
                              void* d_out, int out_size) {
    const float* q = (const float*)d_in[0];
    const float* k = (const float*)d_in[1];
    const float* v = (const float*)d_in[2];
    const int*   w = (const int*)d_in[3];
    const int B = in_sizes[0] / (S_LEN * DIM);
    float* out = (float*)d_out;

    conv_kv_kernel<<<dim3(NT64, B), NT>>>(k, v);

    cudaFuncSetAttribute(swa_mma_kernel, cudaFuncAttributeMaxDynamicSharedMemorySize, SMEM_BYTES);
    dim3 grid(S_LEN / BQ, B);
    swa_mma_kernel<<<grid, NT, SMEM_BYTES>>>(q, w, out);
}

// round 12
// speedup vs baseline: 2.7693x; 1.2738x over previous
#include <cuda_runtime.h>
#include <cuda_fp16.h>
#include <cstdint>
#include <math.h>

#define S_LEN 4096
#define DIM   128
#define BQ    64
#define BK    64
#define NT    256
#define NT64  (S_LEN / 64)
#define TILEB 16384

// K/V pre-converted scratch: [B][tile][K,V][16KB] = 8MB (fp16)
__device__ __align__(16) char g_kv[4 * NT64 * 2 * TILEB];

// per-CTA smem byte offsets (all single-precision fp16 buffers)
#define OQ  0
#define OK  16384
#define OV  32768
#define OP  49152
#define SMEM_BYTES 57344
#define ORS OK
#define OSTG (OK + 1024)

__device__ __forceinline__ uint32_t s2u(const void* p) {
    uint32_t a;
    asm("{ .reg .u64 t; cvta.to.shared.u64 t, %1; cvt.u32.u64 %0, t; }" : "=r"(a) : "l"(p));
    return a;
}
__device__ __forceinline__ void ldm4(uint32_t a, uint32_t* r) {
    asm volatile("ldmatrix.sync.aligned.m8n8.x4.shared.b16 {%0,%1,%2,%3}, [%4];"
                 : "=r"(r[0]), "=r"(r[1]), "=r"(r[2]), "=r"(r[3]) : "r"(a));
}
__device__ __forceinline__ void ldm4t(uint32_t a, uint32_t* r) {
    asm volatile("ldmatrix.sync.aligned.m8n8.x4.trans.shared.b16 {%0,%1,%2,%3}, [%4];"
                 : "=r"(r[0]), "=r"(r[1]), "=r"(r[2]), "=r"(r[3]) : "r"(a));
}
__device__ __forceinline__ void mma_f16(float* c, const uint32_t* a, uint32_t b0, uint32_t b1) {
    asm volatile("mma.sync.aligned.m16n8k16.row.col.f32.f16.f16.f32 "
                 "{%0,%1,%2,%3}, {%4,%5,%6,%7}, {%8,%9}, {%0,%1,%2,%3};"
                 : "+f"(c[0]), "+f"(c[1]), "+f"(c[2]), "+f"(c[3])
                 : "r"(a[0]), "r"(a[1]), "r"(a[2]), "r"(a[3]), "r"(b0), "r"(b1));
}
__device__ __forceinline__ uint32_t h2u(__half2 h) { return *reinterpret_cast<uint32_t*>(&h); }
__device__ __forceinline__ float ex2(float x) {
    float r;
    asm("ex2.approx.f32 %0, %1;" : "=f"(r) : "f"(x));
    return r;
}
__device__ __forceinline__ void cp16(uint32_t dst, const char* src) {
    asm volatile("cp.async.cg.shared.global [%0], [%1], 16;" :: "r"(dst), "l"(src));
}
#define CP_COMMIT() asm volatile("cp.async.commit_group;")
#define CP_WAIT0()  asm volatile("cp.async.wait_group 0;")

// ---- 1-term QK: q (fp16) x K (fp16); each fragment loaded once ----
__device__ __forceinline__ void qk_fused(float (*c)[4], uint32_t qb, uint32_t kb,
                                         bool sk0, bool sk1, uint32_t krow0, uint32_t krow1,
                                         int hi4, int lo7, int cbl, int kk0, int kk1) {
    #pragma unroll
    for (int kk = kk0; kk < kk1; kk++) {
        uint32_t A[4];
        ldm4(qb + (uint32_t)(((2 * kk + hi4) ^ lo7) << 4), A);
        uint32_t kcol = (uint32_t)(((2 * kk + cbl) ^ lo7) << 4);
        if (!sk0) {
            uint32_t b0[4];
            ldm4(kb + krow0 + kcol, b0);
            mma_f16(c[0], A, b0[0], b0[1]); mma_f16(c[1], A, b0[2], b0[3]);
        }
        if (!sk1) {
            uint32_t b1[4];
            ldm4(kb + krow1 + kcol, b1);
            mma_f16(c[2], A, b1[0], b1[1]); mma_f16(c[3], A, b1[2], b1[3]);
        }
    }
}

// ---- 1-term PV: P (fp16) x V (fp16); each fragment loaded once ----
__device__ __forceinline__ void pv_fused(float (*o)[4], uint32_t pb, uint32_t vb,
                                         const bool* skp, int hi4, int lo7, int nh) {
    #pragma unroll
    for (int kk2 = 0; kk2 < 4; kk2++) {
        if (!skp[kk2]) {
            uint32_t ph[4];
            ldm4(pb + (uint32_t)(((2 * kk2 + hi4) ^ lo7) << 4), ph);
            uint32_t vrow = (uint32_t)(kk2 * 16 * 256);
            #pragma unroll
            for (int vp2 = 0; vp2 < 4; vp2++) {
                uint32_t bh[4];
                ldm4t(vb + vrow + (uint32_t)(((nh * 8 + 2 * vp2 + hi4) ^ lo7) << 4), bh);
                mma_f16(o[vp2 * 2],     ph, bh[0], bh[1]);
                mma_f16(o[vp2 * 2 + 1], ph, bh[2], bh[3]);
            }
        }
    }
}

// ================= pre-convert: K,V fp32 -> fp16 swizzled tile images =================
__global__ __launch_bounds__(NT, 4)
void conv_kv_kernel(const float* __restrict__ gk, const float* __restrict__ gv) {
    const int t = blockIdx.x, b = blockIdx.y, tid = threadIdx.x;
    char* dst = g_kv + ((size_t)(b * NT64 + t)) * 2 * TILEB;
    const float4* kg = reinterpret_cast<const float4*>(gk + ((size_t)b * S_LEN + t * 64) * DIM);
    const float4* vg = reinterpret_cast<const float4*>(gv + ((size_t)b * S_LEN + t * 64) * DIM);
    #pragma unroll
    for (int i = 0; i < 8; i++) {
        int idx = tid + i * NT;
        int row = idx >> 5, c4 = idx & 31;
        int chunk = c4 >> 1, sub = (c4 & 1) << 3;
        int off = row * 256 + ((chunk ^ (row & 7)) << 4) + sub;
        float4 kv = kg[idx];
        *reinterpret_cast<uint2*>(dst + off) =
            make_uint2(h2u(__floats2half2_rn(kv.x, kv.y)), h2u(__floats2half2_rn(kv.z, kv.w)));
        float4 vv = vg[idx];
        *reinterpret_cast<uint2*>(dst + TILEB + off) =
            make_uint2(h2u(__floats2half2_rn(vv.x, vv.y)), h2u(__floats2half2_rn(vv.z, vv.w)));
    }
}

// ================= main attention kernel (pipelined, 1-term fp16 MMA) =================
__global__ __launch_bounds__(NT, 2)
void swa_mma_kernel(const float* __restrict__ gq, const int* __restrict__ wptr,
                    float* __restrict__ gout)
{
    extern __shared__ char smc[];
    const uint32_t sb = s2u(smc);
    const int tid = threadIdx.x, lane = tid & 31, wr = tid >> 5;
    const int rg = wr & 3;
    const int nh = wr >> 2;
    const int q0 = blockIdx.x * BQ, b = blockIdx.y;
    const int w = wptr[0];
    const float scale = 1.44269504f * rsqrtf((float)DIM);

    const int il0 = rg * 16 + (lane >> 2);
    const int gr  = q0 + il0;
    const int hi4 = lane >> 4;
    const int lo7 = lane & 7;
    const int cbl = (lane >> 3) & 1;
    const int rbl = (lane & 7) + ((lane >> 4) << 3);

    const uint32_t qb = sb + OQ + (uint32_t)((rg * 16 + (lane & 15)) * 256);
    const uint32_t pb = sb + OP + (uint32_t)((rg * 16 + (lane & 15)) * 128);
    const uint32_t vb = sb + OV + (uint32_t)((lane & 15) * 256);
    const uint32_t krow0 = (uint32_t)(((nh * 2 + 0) * 16 + rbl) * 256);
    const uint32_t krow1 = (uint32_t)(((nh * 2 + 1) * 16 + rbl) * 256);

    int lo = q0 - (w - 1);              if (lo < 0) lo = 0;
    int hi = q0 + BQ - 1 + (w - 1);     if (hi > S_LEN - 1) hi = S_LEN - 1;
    const int t0 = lo >> 6, t1 = hi >> 6;
    const int rlo = q0 + rg * 16, rhi = rlo + 15;

    const char* kvbase = g_kv + ((size_t)b * NT64) * 2 * TILEB;

    // ---- prologue group: K(t0) + V(t0) ----
    {
        const char* src = kvbase + (size_t)t0 * 2 * TILEB;
        #pragma unroll
        for (int i = 0; i < 4; i++) {
            int off = tid * 16 + i * 4096;
            cp16(sb + OK + off, src + off);
        }
        #pragma unroll
        for (int i = 0; i < 4; i++) {
            int off = tid * 16 + i * 4096;
            cp16(sb + OV + off, src + TILEB + off);
        }
        CP_COMMIT();
    }

    // ---- Q -> smem (fp16 single, swizzled), overlaps prologue copies ----
    {
        const float4* qg = reinterpret_cast<const float4*>(gq + ((size_t)b * S_LEN + q0) * DIM);
        #pragma unroll
        for (int i = 0; i < 8; i++) {
            int idx = tid + i * NT;
            int row = idx >> 5, c4 = idx & 31;
            int chunk = c4 >> 1, sub = (c4 & 1) << 3;
            float4 vv = qg[idx];
            int off = row * 256 + ((chunk ^ (row & 7)) << 4) + sub;
            *reinterpret_cast<uint2*>(smc + OQ + off) =
                make_uint2(h2u(__floats2half2_rn(vv.x * scale, vv.y * scale)),
                           h2u(__floats2half2_rn(vv.z * scale, vv.w * scale)));
        }
    }

    float o[8][4];
    #pragma unroll
    for (int n = 0; n < 8; n++)
        #pragma unroll
        for (int e = 0; e < 4; e++) o[n][e] = 0.f;
    float c[4][4];
    #pragma unroll
    for (int n = 0; n < 4; n++)
        #pragma unroll
        for (int e = 0; e < 4; e++) c[n][e] = 0.f;
    float rs0 = 0.f, rs1 = 0.f;

    auto skq_of = [&](int k0t, int np2) {
        int kb0 = k0t + nh * 32 + np2 * 16;
        return (kb0 - rhi >= w) || (rlo - (kb0 + 15) >= w);
    };

    CP_WAIT0();
    __syncthreads();               // Q + K(t0) + V(t0) visible

    // ---- QK(t0) ----
    {
        const int k0 = t0 << 6;
        bool s0 = skq_of(k0, 0), s1 = skq_of(k0, 1);
        qk_fused(c, qb, sb + OK, s0, s1, krow0, krow1, hi4, lo7, cbl, 0, 8);
    }
    __syncthreads();               // K(t0) consumed
    if (t0 < t1) {                 // prefetch K(t0+1)
        const char* src = kvbase + (size_t)(t0 + 1) * 2 * TILEB;
        #pragma unroll
        for (int i = 0; i < 4; i++) {
            int off = tid * 16 + i * 4096;
            cp16(sb + OK + off, src + off);
        }
        CP_COMMIT();
    }

    for (int t = t0; t <= t1; t++) {
        const int k0 = t << 6;
        const bool doQK = (t < t1);
        const int k0n = (t + 1) << 6;
        bool sq0 = doQK ? skq_of(k0n, 0) : true;
        bool sq1 = doQK ? skq_of(k0n, 1) : true;
        bool skp[4];
        #pragma unroll
        for (int kk2 = 0; kk2 < 4; kk2++) {
            int kb0 = k0 + kk2 * 16;
            skp[kk2] = (kb0 - rhi >= w) || (rlo - (kb0 + 15) >= w);
        }

        // ---- mask + exp2 + partial rowsum ----
        float ps0 = 0.f, ps1 = 0.f;
        #pragma unroll
        for (int j = 0; j < 4; j++) {
            int jg = k0 + nh * 32 + j * 8 + ((lane & 3) << 1);
            int d0 = gr - jg;
            float e;
            e = (d0 < w && d0 > -w)         ? ex2(c[j][0]) : 0.f; c[j][0] = e; ps0 += e;
            e = (d0 - 1 < w && d0 - 1 > -w) ? ex2(c[j][1]) : 0.f; c[j][1] = e; ps0 += e;
            e = (d0 + 8 < w && d0 + 8 > -w) ? ex2(c[j][2]) : 0.f; c[j][2] = e; ps1 += e;
            e = (d0 + 7 < w && d0 + 7 > -w) ? ex2(c[j][3]) : 0.f; c[j][3] = e; ps1 += e;
        }
        ps0 += __shfl_xor_sync(0xffffffffu, ps0, 1);
        ps0 += __shfl_xor_sync(0xffffffffu, ps0, 2);
        ps1 += __shfl_xor_sync(0xffffffffu, ps1, 1);
        ps1 += __shfl_xor_sync(0xffffffffu, ps1, 2);
        rs0 += ps0; rs1 += ps1;

        // ---- P(t) -> smem (fp16 single), then zero c ----
        #pragma unroll
        for (int j = 0; j < 4; j++) {
            int off0 = il0 * 128 + (((nh * 4 + j) ^ (il0 & 7)) << 4) + ((lane & 3) << 2);
            *reinterpret_cast<uint32_t*>(smc + OP + off0) =
                h2u(__floats2half2_rn(c[j][0], c[j][1]));
            int r1 = il0 + 8;
            int off1 = r1 * 128 + (((nh * 4 + j) ^ (r1 & 7)) << 4) + ((lane & 3) << 2);
            *reinterpret_cast<uint32_t*>(smc + OP + off1) =
                h2u(__floats2half2_rn(c[j][2], c[j][3]));
        }
        #pragma unroll
        for (int n = 0; n < 4; n++)
            #pragma unroll
            for (int e = 0; e < 4; e++) c[n][e] = 0.f;

        CP_WAIT0();                // V(t) [+K(t+1)] arrived
        __syncthreads();           // P + V(t) + K(t+1) visible CTA-wide

        // ---- fused MMA phase: QK(t+1) halves around PV(t) ----
        if (doQK) qk_fused(c, qb, sb + OK, sq0, sq1, krow0, krow1, hi4, lo7, cbl, 0, 4);
        pv_fused(o, pb, vb, skp, hi4, lo7, nh);
        if (doQK) qk_fused(c, qb, sb + OK, sq0, sq1, krow0, krow1, hi4, lo7, cbl, 4, 8);

        __syncthreads();           // K(t+1), V(t), P(t) consumed

        if (t < t1) {              // prefetch V(t+1) [+ K(t+2)]
            const char* srcv = kvbase + (size_t)(t + 1) * 2 * TILEB;
            #pragma unroll
            for (int i = 0; i < 4; i++) {
                int off = tid * 16 + i * 4096;
                cp16(sb + OV + off, srcv + TILEB + off);
            }
            if (t + 1 < t1) {
                const char* srck = kvbase + (size_t)(t + 2) * 2 * TILEB;
                #pragma unroll
                for (int i = 0; i < 4; i++) {
                    int off = tid * 16 + i * 4096;
                    cp16(sb + OK + off, srck + off);
                }
            }
            CP_COMMIT();
        }
    }

    // ================= rowsum combine + normalize + store =================
    __syncthreads();
    float* rsb = reinterpret_cast<float*>(smc + ORS);
    if ((lane & 3) == 0) {
        rsb[nh * 64 + il0]     = rs0;
        rsb[nh * 64 + il0 + 8] = rs1;
    }
    __syncthreads();
    const float inv0 = 1.0f / (rsb[il0]     + rsb[64 + il0]);
    const float inv1 = 1.0f / (rsb[il0 + 8] + rsb[64 + il0 + 8]);

    float* stg = reinterpret_cast<float*>(smc + OSTG);
    const int jd = (lane & 3) << 1;
    #pragma unroll
    for (int n = 0; n < 8; n++) {
        int col = nh * 64 + n * 8 + jd;
        *reinterpret_cast<float2*>(&stg[il0 * 132 + col]) =
            make_float2(o[n][0] * inv0, o[n][1] * inv0);
        *reinterpret_cast<float2*>(&stg[(il0 + 8) * 132 + col]) =
            make_float2(o[n][2] * inv1, o[n][3] * inv1);
    }
    __syncthreads();
    float4* og = reinterpret_cast<float4*>(gout + ((size_t)b * S_LEN + q0) * DIM);
    #pragma unroll
    for (int i = 0; i < 8; i++) {
        int idx = tid + i * NT;
        int row = idx >> 5, c4 = idx & 31;
        og[idx] = *reinterpret_cast<float4*>(&stg[row * 132 + c4 * 4]);
    }
}

extern "C" void kernel_launch(void* const* d_in, const int* in_sizes, int n_in,
                              void* d_out, int out_size) {
    const float* q = (const float*)d_in[0];
    const float* k = (const float*)d_in[1];
    const float* v = (const float*)d_in[2];
    const int*   w = (const int*)d_in[3];
    const int B = in_sizes[0] / (S_LEN * DIM);
    float* out = (float*)d_out;

    conv_kv_kernel<<<dim3(NT64, B), NT>>>(k, v);

    cudaFuncSetAttribute(swa_mma_kernel, cudaFuncAttributeMaxDynamicSharedMemorySize, SMEM_BYTES);
    dim3 grid(S_LEN / BQ, B);
    swa_mma_kernel<<<grid, NT, SMEM_BYTES>>>(q, w, out);
}

// round 13
// speedup vs baseline: 2.8069x; 1.0136x over previous
#include <cuda_runtime.h>
#include <cuda_fp16.h>
#include <cstdint>
#include <math.h>

#define S_LEN 4096
#define DIM   128
#define BQ    64
#define BK    64
#define NT    256
#define NT64  (S_LEN / 64)
#define TILEB 16384

// K/V pre-converted scratch: [B][tile][K,V][16KB] = 8MB (fp16)
__device__ __align__(16) char g_kv[4 * NT64 * 2 * TILEB];

// per-CTA smem byte offsets: Q | K0 K1 | V0 V1 | P0 P1
#define OQ     0
#define OK(p)  (16384 + (p) * 16384)
#define OV(p)  (49152 + (p) * 16384)
#define OP(p)  (81920 + (p) * 8192)
#define SMEM_BYTES 98304
#define ORS  16384             // epilogue reuse (K region dead)
#define OSTG (16384 + 1024)

__device__ __forceinline__ uint32_t s2u(const void* p) {
    uint32_t a;
    asm("{ .reg .u64 t; cvta.to.shared.u64 t, %1; cvt.u32.u64 %0, t; }" : "=r"(a) : "l"(p));
    return a;
}
__device__ __forceinline__ void ldm4(uint32_t a, uint32_t* r) {
    asm volatile("ldmatrix.sync.aligned.m8n8.x4.shared.b16 {%0,%1,%2,%3}, [%4];"
                 : "=r"(r[0]), "=r"(r[1]), "=r"(r[2]), "=r"(r[3]) : "r"(a));
}
__device__ __forceinline__ void ldm4t(uint32_t a, uint32_t* r) {
    asm volatile("ldmatrix.sync.aligned.m8n8.x4.trans.shared.b16 {%0,%1,%2,%3}, [%4];"
                 : "=r"(r[0]), "=r"(r[1]), "=r"(r[2]), "=r"(r[3]) : "r"(a));
}
__device__ __forceinline__ void mma_f16(float* c, const uint32_t* a, uint32_t b0, uint32_t b1) {
    asm volatile("mma.sync.aligned.m16n8k16.row.col.f32.f16.f16.f32 "
                 "{%0,%1,%2,%3}, {%4,%5,%6,%7}, {%8,%9}, {%0,%1,%2,%3};"
                 : "+f"(c[0]), "+f"(c[1]), "+f"(c[2]), "+f"(c[3])
                 : "r"(a[0]), "r"(a[1]), "r"(a[2]), "r"(a[3]), "r"(b0), "r"(b1));
}
__device__ __forceinline__ uint32_t h2u(__half2 h) { return *reinterpret_cast<uint32_t*>(&h); }
__device__ __forceinline__ float ex2(float x) {
    float r;
    asm("ex2.approx.f32 %0, %1;" : "=f"(r) : "f"(x));
    return r;
}
__device__ __forceinline__ void cp16(uint32_t dst, const char* src) {
    asm volatile("cp.async.cg.shared.global [%0], [%1], 16;" :: "r"(dst), "l"(src));
}
#define CP_COMMIT() asm volatile("cp.async.commit_group;")
#define CP_WAIT0()  asm volatile("cp.async.wait_group 0;")
#define CP_WAIT1()  asm volatile("cp.async.wait_group 1;")

// ---- 1-term QK ----
__device__ __forceinline__ void qk_fused(float (*c)[4], uint32_t qb, uint32_t kb,
                                         bool sk0, bool sk1, uint32_t krow0, uint32_t krow1,
                                         int hi4, int lo7, int cbl, int kk0, int kk1) {
    #pragma unroll
    for (int kk = kk0; kk < kk1; kk++) {
        uint32_t A[4];
        ldm4(qb + (uint32_t)(((2 * kk + hi4) ^ lo7) << 4), A);
        uint32_t kcol = (uint32_t)(((2 * kk + cbl) ^ lo7) << 4);
        if (!sk0) {
            uint32_t b0[4];
            ldm4(kb + krow0 + kcol, b0);
            mma_f16(c[0], A, b0[0], b0[1]); mma_f16(c[1], A, b0[2], b0[3]);
        }
        if (!sk1) {
            uint32_t b1[4];
            ldm4(kb + krow1 + kcol, b1);
            mma_f16(c[2], A, b1[0], b1[1]); mma_f16(c[3], A, b1[2], b1[3]);
        }
    }
}

// ---- 1-term PV ----
__device__ __forceinline__ void pv_fused(float (*o)[4], uint32_t pb, uint32_t vb,
                                         const bool* skp, int hi4, int lo7, int nh) {
    #pragma unroll
    for (int kk2 = 0; kk2 < 4; kk2++) {
        if (!skp[kk2]) {
            uint32_t ph[4];
            ldm4(pb + (uint32_t)(((2 * kk2 + hi4) ^ lo7) << 4), ph);
            uint32_t vrow = (uint32_t)(kk2 * 16 * 256);
            #pragma unroll
            for (int vp2 = 0; vp2 < 4; vp2++) {
                uint32_t bh[4];
                ldm4t(vb + vrow + (uint32_t)(((nh * 8 + 2 * vp2 + hi4) ^ lo7) << 4), bh);
                mma_f16(o[vp2 * 2],     ph, bh[0], bh[1]);
                mma_f16(o[vp2 * 2 + 1], ph, bh[2], bh[3]);
            }
        }
    }
}

// ================= pre-convert: K,V fp32 -> fp16 swizzled tile images =================
__global__ __launch_bounds__(NT, 4)
void conv_kv_kernel(const float* __restrict__ gk, const float* __restrict__ gv) {
    const int t = blockIdx.x, b = blockIdx.y, tid = threadIdx.x;
    char* dst = g_kv + ((size_t)(b * NT64 + t)) * 2 * TILEB;
    const float4* kg = reinterpret_cast<const float4*>(gk + ((size_t)b * S_LEN + t * 64) * DIM);
    const float4* vg = reinterpret_cast<const float4*>(gv + ((size_t)b * S_LEN + t * 64) * DIM);
    #pragma unroll
    for (int i = 0; i < 8; i++) {
        int idx = tid + i * NT;
        int row = idx >> 5, c4 = idx & 31;
        int chunk = c4 >> 1, sub = (c4 & 1) << 3;
        int off = row * 256 + ((chunk ^ (row & 7)) << 4) + sub;
        float4 kv = kg[idx];
        *reinterpret_cast<uint2*>(dst + off) =
            make_uint2(h2u(__floats2half2_rn(kv.x, kv.y)), h2u(__floats2half2_rn(kv.z, kv.w)));
        float4 vv = vg[idx];
        *reinterpret_cast<uint2*>(dst + TILEB + off) =
            make_uint2(h2u(__floats2half2_rn(vv.x, vv.y)), h2u(__floats2half2_rn(vv.z, vv.w)));
    }
}

// ================= main attention kernel (1 barrier/iter, double-buffered K/V/P) =================
__global__ __launch_bounds__(NT, 2)
void swa_mma_kernel(const float* __restrict__ gq, const int* __restrict__ wptr,
                    float* __restrict__ gout)
{
    extern __shared__ char smc[];
    const uint32_t sb = s2u(smc);
    const int tid = threadIdx.x, lane = tid & 31, wr = tid >> 5;
    const int rg = wr & 3;
    const int nh = wr >> 2;
    const int q0 = blockIdx.x * BQ, b = blockIdx.y;
    const int w = wptr[0];
    const float scale = 1.44269504f * rsqrtf((float)DIM);

    const int il0 = rg * 16 + (lane >> 2);
    const int gr  = q0 + il0;
    const int hi4 = lane >> 4;
    const int lo7 = lane & 7;
    const int cbl = (lane >> 3) & 1;
    const int rbl = (lane & 7) + ((lane >> 4) << 3);

    const uint32_t qb    = sb + OQ + (uint32_t)((rg * 16 + (lane & 15)) * 256);
    const uint32_t pboff = (uint32_t)((rg * 16 + (lane & 15)) * 128);
    const uint32_t vboff = (uint32_t)((lane & 15) * 256);
    const uint32_t krow0 = (uint32_t)(((nh * 2 + 0) * 16 + rbl) * 256);
    const uint32_t krow1 = (uint32_t)(((nh * 2 + 1) * 16 + rbl) * 256);

    int lo = q0 - (w - 1);              if (lo < 0) lo = 0;
    int hi = q0 + BQ - 1 + (w - 1);     if (hi > S_LEN - 1) hi = S_LEN - 1;
    const int t0 = lo >> 6, t1 = hi >> 6;
    const int rlo = q0 + rg * 16, rhi = rlo + 15;

    const char* kvbase = g_kv + ((size_t)b * NT64) * 2 * TILEB;

    auto skq_of = [&](int k0t, int np2) {
        int kb0 = k0t + nh * 32 + np2 * 16;
        return (kb0 - rhi >= w) || (rlo - (kb0 + 15) >= w);
    };

    // ---- prologue: group A = {K(t0), V(t0)}; group B = {K(t0+1)} ----
    {
        const char* src = kvbase + (size_t)t0 * 2 * TILEB;
        #pragma unroll
        for (int i = 0; i < 4; i++) {
            int off = tid * 16 + i * 4096;
            cp16(sb + OK(t0 & 1) + off, src + off);
        }
        #pragma unroll
        for (int i = 0; i < 4; i++) {
            int off = tid * 16 + i * 4096;
            cp16(sb + OV(t0 & 1) + off, src + TILEB + off);
        }
        CP_COMMIT();
    }
    // Q -> smem (fp16, swizzled) — overlaps group A
    {
        const float4* qg = reinterpret_cast<const float4*>(gq + ((size_t)b * S_LEN + q0) * DIM);
        #pragma unroll
        for (int i = 0; i < 8; i++) {
            int idx = tid + i * NT;
            int row = idx >> 5, c4 = idx & 31;
            int chunk = c4 >> 1, sub = (c4 & 1) << 3;
            float4 vv = qg[idx];
            int off = row * 256 + ((chunk ^ (row & 7)) << 4) + sub;
            *reinterpret_cast<uint2*>(smc + OQ + off) =
                make_uint2(h2u(__floats2half2_rn(vv.x * scale, vv.y * scale)),
                           h2u(__floats2half2_rn(vv.z * scale, vv.w * scale)));
        }
    }
    if (t0 < t1) {
        const char* src = kvbase + (size_t)(t0 + 1) * 2 * TILEB;
        #pragma unroll
        for (int i = 0; i < 4; i++) {
            int off = tid * 16 + i * 4096;
            cp16(sb + OK((t0 + 1) & 1) + off, src + off);
        }
    }
    CP_COMMIT();

    float o[8][4];
    #pragma unroll
    for (int n = 0; n < 8; n++)
        #pragma unroll
        for (int e = 0; e < 4; e++) o[n][e] = 0.f;
    float c[4][4];
    #pragma unroll
    for (int n = 0; n < 4; n++)
        #pragma unroll
        for (int e = 0; e < 4; e++) c[n][e] = 0.f;
    float rs0 = 0.f, rs1 = 0.f;

    CP_WAIT1();                 // group A done (K(t0), V(t0))
    __syncthreads();            // + Q visible

    // ---- QK(t0) ----
    bool sp0, sp1;
    {
        const int k0 = t0 << 6;
        sp0 = skq_of(k0, 0); sp1 = skq_of(k0, 1);
        qk_fused(c, qb, sb + OK(t0 & 1), sp0, sp1, krow0, krow1, hi4, lo7, cbl, 0, 8);
    }

    for (int t = t0; t <= t1; t++) {
        const int k0 = t << 6;
        const int par = t & 1;
        const bool doQK = (t < t1);
        const int k0n = (t + 1) << 6;
        bool sq0 = doQK ? skq_of(k0n, 0) : true;
        bool sq1 = doQK ? skq_of(k0n, 1) : true;
        bool skp[4];
        #pragma unroll
        for (int kk2 = 0; kk2 < 4; kk2++) {
            int kb0 = k0 + kk2 * 16;
            skp[kk2] = (kb0 - rhi >= w) || (rlo - (kb0 + 15) >= w);
        }

        // ---- mask + exp2 + partial rowsum (skip fully-masked chunks) ----
        float ps0 = 0.f, ps1 = 0.f;
        if (!sp0) {
            #pragma unroll
            for (int j = 0; j < 2; j++) {
                int jg = k0 + nh * 32 + j * 8 + ((lane & 3) << 1);
                int d0 = gr - jg;
                float e;
                e = (d0 < w && d0 > -w)         ? ex2(c[j][0]) : 0.f; c[j][0] = e; ps0 += e;
                e = (d0 - 1 < w && d0 - 1 > -w) ? ex2(c[j][1]) : 0.f; c[j][1] = e; ps0 += e;
                e = (d0 + 8 < w && d0 + 8 > -w) ? ex2(c[j][2]) : 0.f; c[j][2] = e; ps1 += e;
                e = (d0 + 7 < w && d0 + 7 > -w) ? ex2(c[j][3]) : 0.f; c[j][3] = e; ps1 += e;
            }
        }
        if (!sp1) {
            #pragma unroll
            for (int j = 2; j < 4; j++) {
                int jg = k0 + nh * 32 + j * 8 + ((lane & 3) << 1);
                int d0 = gr - jg;
                float e;
                e = (d0 < w && d0 > -w)         ? ex2(c[j][0]) : 0.f; c[j][0] = e; ps0 += e;
                e = (d0 - 1 < w && d0 - 1 > -w) ? ex2(c[j][1]) : 0.f; c[j][1] = e; ps0 += e;
                e = (d0 + 8 < w && d0 + 8 > -w) ? ex2(c[j][2]) : 0.f; c[j][2] = e; ps1 += e;
                e = (d0 + 7 < w && d0 + 7 > -w) ? ex2(c[j][3]) : 0.f; c[j][3] = e; ps1 += e;
            }
        }
        ps0 += __shfl_xor_sync(0xffffffffu, ps0, 1);
        ps0 += __shfl_xor_sync(0xffffffffu, ps0, 2);
        ps1 += __shfl_xor_sync(0xffffffffu, ps1, 1);
        ps1 += __shfl_xor_sync(0xffffffffu, ps1, 2);
        rs0 += ps0; rs1 += ps1;

        // ---- P(t) -> P[par] (safe pre-barrier: readers use P[1-par]) ----
        #pragma unroll
        for (int j = 0; j < 4; j++) {
            if ((j < 2) ? sp0 : sp1) continue;
            int off0 = il0 * 128 + (((nh * 4 + j) ^ (il0 & 7)) << 4) + ((lane & 3) << 2);
            *reinterpret_cast<uint32_t*>(smc + OP(par) + off0) =
                h2u(__floats2half2_rn(c[j][0], c[j][1]));
            int r1 = il0 + 8;
            int off1 = r1 * 128 + (((nh * 4 + j) ^ (r1 & 7)) << 4) + ((lane & 3) << 2);
            *reinterpret_cast<uint32_t*>(smc + OP(par) + off1) =
                h2u(__floats2half2_rn(c[j][2], c[j][3]));
        }
        #pragma unroll
        for (int n = 0; n < 4; n++)
            #pragma unroll
            for (int e = 0; e < 4; e++) c[n][e] = 0.f;

        CP_WAIT0();                 // V(t), K(t+1) landed (thread-local)
        __syncthreads();            // THE barrier: P(t)+copies visible; MMA(t-1) all done

        // ---- post-barrier prefetch: {V(t+1), K(t+2)} one group (write-safe now) ----
        if (t < t1) {
            const char* srcv = kvbase + (size_t)(t + 1) * 2 * TILEB;
            #pragma unroll
            for (int i = 0; i < 4; i++) {
                int off = tid * 16 + i * 4096;
                cp16(sb + OV((t + 1) & 1) + off, srcv + TILEB + off);
            }
            if (t + 2 <= t1) {
                const char* srck = kvbase + (size_t)(t + 2) * 2 * TILEB;
                #pragma unroll
                for (int i = 0; i < 4; i++) {
                    int off = tid * 16 + i * 4096;
                    cp16(sb + OK(par) + off, srck + off);
                }
            }
            CP_COMMIT();
        }

        // ---- fused MMA phase: QK(t+1) halves around PV(t) ----
        const uint32_t pb = sb + OP(par) + pboff;
        const uint32_t vb = sb + OV(par) + vboff;
        const uint32_t kbn = sb + OK((t + 1) & 1);
        if (doQK) qk_fused(c, qb, kbn, sq0, sq1, krow0, krow1, hi4, lo7, cbl, 0, 4);
        pv_fused(o, pb, vb, skp, hi4, lo7, nh);
        if (doQK) qk_fused(c, qb, kbn, sq0, sq1, krow0, krow1, hi4, lo7, cbl, 4, 8);

        sp0 = sq0; sp1 = sq1;
    }

    // ================= rowsum combine + normalize + store =================
    __syncthreads();
    float* rsb = reinterpret_cast<float*>(smc + ORS);
    if ((lane & 3) == 0) {
        rsb[nh * 64 + il0]     = rs0;
        rsb[nh * 64 + il0 + 8] = rs1;
    }
    __syncthreads();
    const float inv0 = 1.0f / (rsb[il0]     + rsb[64 + il0]);
    const float inv1 = 1.0f / (rsb[il0 + 8] + rsb[64 + il0 + 8]);

    float* stg = reinterpret_cast<float*>(smc + OSTG);
    const int jd = (lane & 3) << 1;
    #pragma unroll
    for (int n = 0; n < 8; n++) {
        int col = nh * 64 + n * 8 + jd;
        *reinterpret_cast<float2*>(&stg[il0 * 132 + col]) =
            make_float2(o[n][0] * inv0, o[n][1] * inv0);
        *reinterpret_cast<float2*>(&stg[(il0 + 8) * 132 + col]) =
            make_float2(o[n][2] * inv1, o[n][3] * inv1);
    }
    __syncthreads();
    float4* og = reinterpret_cast<float4*>(gout + ((size_t)b * S_LEN + q0) * DIM);
    #pragma unroll
    for (int i = 0; i < 8; i++) {
        int idx = tid + i * NT;
        int row = idx >> 5, c4 = idx & 31;
        og[idx] = *reinterpret_cast<float4*>(&stg[row * 132 + c4 * 4]);
    }
}

extern "C" void kernel_launch(void* const* d_in, const int* in_sizes, int n_in,
                              void* d_out, int out_size) {
    const float* q = (const float*)d_in[0];
    const float* k = (const float*)d_in[1];
    const float* v = (const float*)d_in[2];
    const int*   w = (const int*)d_in[3];
    const int B = in_sizes[0] / (S_LEN * DIM);
    float* out = (float*)d_out;

    conv_kv_kernel<<<dim3(NT64, B), NT>>>(k, v);

    cudaFuncSetAttribute(swa_mma_kernel, cudaFuncAttributeMaxDynamicSharedMemorySize, SMEM_BYTES);
    dim3 grid(S_LEN / BQ, B);
    swa_mma_kernel<<<grid, NT, SMEM_BYTES>>>(q, w, out);
}